// round 2
// baseline (speedup 1.0000x reference)
#include <cuda_runtime.h>

// Problem constants
#define BSZ 2
#define SEQ 2048
#define DMODEL 1024
#define NHEAD 16
#define DHEAD 64

constexpr int GM = BSZ * SEQ;     // 4096 rows for projections
constexpr int GN = DMODEL;        // 1024
constexpr int GK = DMODEL;        // 1024

// Scratch (allocation-free: static __device__ globals)
__device__ float g_q[BSZ * NHEAD * SEQ * DHEAD];
__device__ float g_k[BSZ * NHEAD * SEQ * DHEAD];
__device__ float g_v[BSZ * NHEAD * SEQ * DHEAD];
__device__ float g_ctx[BSZ * SEQ * DMODEL];

// ---------------------------------------------------------------------------
// SGEMM: C = A @ W^T + bias.  A:[GM,GK], W:[GN,GK], bias:[GN].
// HEAD=true scatters output into [B,H,S,DK] head layout; else row-major [GM,GN].
// 64x64 block tile, 16-deep k-step, 256 threads, 4x4 per-thread micro-tile.
// ---------------------------------------------------------------------------
template <bool HEAD>
__global__ void __launch_bounds__(256) gemm_bias_kernel(
    const float* __restrict__ A, const float* __restrict__ W,
    const float* __restrict__ bias, float* __restrict__ C)
{
    __shared__ float As[16][68];   // As[k][m]
    __shared__ float Bs[16][68];   // Bs[k][n]

    const int tid = threadIdx.x;
    const int tx = tid & 15;          // n-group
    const int ty = tid >> 4;          // m-group
    const int m0 = blockIdx.y * 64;
    const int n0 = blockIdx.x * 64;

    // cooperative load indices: each thread loads one float4 of A and W per step
    const int lr = tid >> 2;          // row in tile 0..63
    const int lk = (tid & 3) * 4;     // k offset 0,4,8,12

    float acc[4][4];
#pragma unroll
    for (int i = 0; i < 4; i++)
#pragma unroll
        for (int j = 0; j < 4; j++) acc[i][j] = 0.f;

    for (int k0 = 0; k0 < GK; k0 += 16) {
        float4 av = *reinterpret_cast<const float4*>(&A[(size_t)(m0 + lr) * GK + k0 + lk]);
        float4 wv = *reinterpret_cast<const float4*>(&W[(size_t)(n0 + lr) * GK + k0 + lk]);
        As[lk + 0][lr] = av.x; As[lk + 1][lr] = av.y;
        As[lk + 2][lr] = av.z; As[lk + 3][lr] = av.w;
        Bs[lk + 0][lr] = wv.x; Bs[lk + 1][lr] = wv.y;
        Bs[lk + 2][lr] = wv.z; Bs[lk + 3][lr] = wv.w;
        __syncthreads();

#pragma unroll
        for (int kk = 0; kk < 16; kk++) {
            float ar[4], br[4];
            *reinterpret_cast<float4*>(ar) =
                *reinterpret_cast<const float4*>(&As[kk][ty * 4]);
            *reinterpret_cast<float4*>(br) =
                *reinterpret_cast<const float4*>(&Bs[kk][tx * 4]);
#pragma unroll
            for (int i = 0; i < 4; i++)
#pragma unroll
                for (int j = 0; j < 4; j++)
                    acc[i][j] += ar[i] * br[j];
        }
        __syncthreads();
    }

#pragma unroll
    for (int i = 0; i < 4; i++) {
        const int row = m0 + ty * 4 + i;
#pragma unroll
        for (int j = 0; j < 4; j++) {
            const int col = n0 + tx * 4 + j;
            const float val = acc[i][j] + bias[col];
            if (HEAD) {
                const int b = row / SEQ, s = row % SEQ;
                const int h = col / DHEAD, d = col % DHEAD;
                C[(((size_t)b * NHEAD + h) * SEQ + s) * DHEAD + d] = val;
            } else {
                C[(size_t)row * GN + col] = val;
            }
        }
    }
}

// ---------------------------------------------------------------------------
// Flash attention (causal).  Q,K,V in [B*H][S][DK] layout.
// Grid: (S/64, B*H). 256 threads. 64q x 64k tiles, online softmax.
// Output written to g_ctx in [B,S,D] layout for the final projection.
// ---------------------------------------------------------------------------
__global__ void __launch_bounds__(256) attn_kernel(
    const float* __restrict__ Q, const float* __restrict__ K,
    const float* __restrict__ V, float* __restrict__ O)
{
    extern __shared__ float sm[];
    float* Qs = sm;                // [64][68], Qs[d][q]
    float* Ks = sm + 64 * 68;      // [64][68], Ks[d][k]
    float* Vs = sm + 2 * 64 * 68;  // [64][68], Vs[k][d]
    float* Ps = sm + 3 * 64 * 68;  // [64][68], Ps[k][q]

    const int tid = threadIdx.x;
    const int tx = tid & 15;
    const int ty = tid >> 4;
    const int q0 = ty * 4;     // this thread's query rows q0..q0+3
    const int c0 = tx * 4;     // key cols (scores) / dim cols (PV)
    const int bh = blockIdx.y;
    const int qb = blockIdx.x;
    const size_t base = (size_t)bh * SEQ * DHEAD;

    // Load Q tile transposed: Qs[d][q]
#pragma unroll
    for (int it = 0; it < 16; it++) {
        const int e = tid + it * 256;
        const int r = e >> 6, d = e & 63;
        Qs[d * 68 + r] = Q[base + (size_t)(qb * 64 + r) * DHEAD + d];
    }

    float m_i[4], l_i[4], acc[4][4];
#pragma unroll
    for (int i = 0; i < 4; i++) {
        m_i[i] = -1e30f;
        l_i[i] = 0.f;
#pragma unroll
        for (int j = 0; j < 4; j++) acc[i][j] = 0.f;
    }

    for (int kb = 0; kb <= qb; kb++) {
        __syncthreads();   // previous iter's smem reads done (also covers Qs load)
#pragma unroll
        for (int it = 0; it < 16; it++) {
            const int e = tid + it * 256;
            const int r = e >> 6, d = e & 63;
            const size_t g = base + (size_t)(kb * 64 + r) * DHEAD + d;
            Ks[d * 68 + r] = K[g];
            Vs[r * 68 + d] = V[g];
        }
        __syncthreads();

        // Scores: s[i][j] = <Q row q0+i, K row c0+j>
        float s[4][4];
#pragma unroll
        for (int i = 0; i < 4; i++)
#pragma unroll
            for (int j = 0; j < 4; j++) s[i][j] = 0.f;

#pragma unroll 8
        for (int d = 0; d < 64; d++) {
            float qr[4], kr[4];
            *reinterpret_cast<float4*>(qr) =
                *reinterpret_cast<const float4*>(&Qs[d * 68 + q0]);
            *reinterpret_cast<float4*>(kr) =
                *reinterpret_cast<const float4*>(&Ks[d * 68 + c0]);
#pragma unroll
            for (int i = 0; i < 4; i++)
#pragma unroll
                for (int j = 0; j < 4; j++)
                    s[i][j] += qr[i] * kr[j];
        }

        const float scale = 0.125f;   // 1/sqrt(64)
        const bool diag = (kb == qb);
#pragma unroll
        for (int i = 0; i < 4; i++)
#pragma unroll
            for (int j = 0; j < 4; j++) {
                s[i][j] *= scale;
                if (diag && (c0 + j > q0 + i)) s[i][j] = -1e30f;
            }

        // Row max over the 16 tx-threads that share each row
        float mloc[4];
#pragma unroll
        for (int i = 0; i < 4; i++)
            mloc[i] = fmaxf(fmaxf(s[i][0], s[i][1]), fmaxf(s[i][2], s[i][3]));
#pragma unroll
        for (int off = 1; off < 16; off <<= 1)
#pragma unroll
            for (int i = 0; i < 4; i++)
                mloc[i] = fmaxf(mloc[i], __shfl_xor_sync(0xffffffffu, mloc[i], off));

        float alpha[4];
#pragma unroll
        for (int i = 0; i < 4; i++) {
            const float mn = fmaxf(m_i[i], mloc[i]);
            alpha[i] = __expf(m_i[i] - mn);
            m_i[i] = mn;
        }

        float rs[4];
#pragma unroll
        for (int i = 0; i < 4; i++) {
            float r = 0.f;
#pragma unroll
            for (int j = 0; j < 4; j++) {
                s[i][j] = __expf(s[i][j] - m_i[i]);
                r += s[i][j];
            }
            rs[i] = r;
        }
#pragma unroll
        for (int off = 1; off < 16; off <<= 1)
#pragma unroll
            for (int i = 0; i < 4; i++)
                rs[i] += __shfl_xor_sync(0xffffffffu, rs[i], off);
#pragma unroll
        for (int i = 0; i < 4; i++) {
            l_i[i] = l_i[i] * alpha[i] + rs[i];
#pragma unroll
            for (int j = 0; j < 4; j++) acc[i][j] *= alpha[i];
        }

        // Store P transposed: Ps[k][q]
#pragma unroll
        for (int j = 0; j < 4; j++) {
            float4 pv = make_float4(s[0][j], s[1][j], s[2][j], s[3][j]);
            *reinterpret_cast<float4*>(&Ps[(c0 + j) * 68 + q0]) = pv;
        }
        __syncthreads();

        // acc += P @ V
#pragma unroll 8
        for (int k = 0; k < 64; k++) {
            float pr[4], vr[4];
            *reinterpret_cast<float4*>(pr) =
                *reinterpret_cast<const float4*>(&Ps[k * 68 + q0]);
            *reinterpret_cast<float4*>(vr) =
                *reinterpret_cast<const float4*>(&Vs[k * 68 + c0]);
#pragma unroll
            for (int i = 0; i < 4; i++)
#pragma unroll
                for (int j = 0; j < 4; j++)
                    acc[i][j] += pr[i] * vr[j];
        }
    }

    // Epilogue: normalize and scatter to [B,S,D]
    const int b = bh / NHEAD, h = bh % NHEAD;
#pragma unroll
    for (int i = 0; i < 4; i++) {
        const float inv = 1.f / l_i[i];
        const int srow = qb * 64 + q0 + i;
        float* orow = O + ((size_t)b * SEQ + srow) * DMODEL + h * DHEAD;
#pragma unroll
        for (int j = 0; j < 4; j++)
            orow[c0 + j] = acc[i][j] * inv;
    }
}

// ---------------------------------------------------------------------------
extern "C" void kernel_launch(void* const* d_in, const int* in_sizes, int n_in,
                              void* d_out, int out_size)
{
    const float* q   = (const float*)d_in[0];
    const float* k   = (const float*)d_in[1];
    const float* v   = (const float*)d_in[2];
    // d_in[3] = mask (causal, known statically) -- unused
    const float* w_q = (const float*)d_in[4];
    const float* b_q = (const float*)d_in[5];
    const float* w_k = (const float*)d_in[6];
    const float* b_k = (const float*)d_in[7];
    const float* w_v = (const float*)d_in[8];
    const float* b_v = (const float*)d_in[9];
    const float* w_o = (const float*)d_in[10];
    const float* b_o = (const float*)d_in[11];
    float* out = (float*)d_out;

    float *gq, *gk, *gv, *gctx;
    cudaGetSymbolAddress((void**)&gq,   g_q);
    cudaGetSymbolAddress((void**)&gk,   g_k);
    cudaGetSymbolAddress((void**)&gv,   g_v);
    cudaGetSymbolAddress((void**)&gctx, g_ctx);

    const dim3 gGemm(GN / 64, GM / 64);   // (16, 64)
    gemm_bias_kernel<true><<<gGemm, 256>>>(q, w_q, b_q, gq);
    gemm_bias_kernel<true><<<gGemm, 256>>>(k, w_k, b_k, gk);
    gemm_bias_kernel<true><<<gGemm, 256>>>(v, w_v, b_v, gv);

    const int smem = 4 * 64 * 68 * sizeof(float);   // 69632 B
    cudaFuncSetAttribute(attn_kernel,
                         cudaFuncAttributeMaxDynamicSharedMemorySize, smem);
    attn_kernel<<<dim3(SEQ / 64, BSZ * NHEAD), 256, smem>>>(gq, gk, gv, gctx);

    gemm_bias_kernel<false><<<gGemm, 256>>>(gctx, w_o, b_o, out);
}

// round 6
// speedup vs baseline: 1.5312x; 1.5312x over previous
#include <cuda_runtime.h>
#include <cuda_bf16.h>
#include <cstdint>

#define BSZ 2
#define SEQ 2048
#define DMODEL 1024
#define NHEAD 16
#define DHEAD 64

constexpr int GM = BSZ * SEQ;     // 4096
constexpr int GN = DMODEL;        // 1024
constexpr int GK = DMODEL;        // 1024

// ---------------- scratch (allocation-free device globals) ----------------
__device__ float g_q[BSZ * NHEAD * SEQ * DHEAD];
__device__ float g_k[BSZ * NHEAD * SEQ * DHEAD];
__device__ float g_v[BSZ * NHEAD * SEQ * DHEAD];
__device__ float g_ctx[BSZ * SEQ * DMODEL];

__device__ __nv_bfloat16 g_ah[3][GM * GK];   // q,k,v inputs hi
__device__ __nv_bfloat16 g_al[3][GM * GK];   // q,k,v inputs lo
__device__ __nv_bfloat16 g_wh[4][GN * GK];   // w_q,w_k,w_v,w_o hi
__device__ __nv_bfloat16 g_wl[4][GN * GK];   // lo
__device__ __nv_bfloat16 g_ch[GM * GK];      // ctx hi
__device__ __nv_bfloat16 g_cl[GM * GK];      // ctx lo

// ---------------------------- PTX helpers ---------------------------------
__device__ __forceinline__ uint32_t smem_u32(const void* p) {
    uint32_t a;
    asm("{ .reg .u64 t; cvta.to.shared.u64 t, %1; cvt.u32.u64 %0, t; }"
        : "=r"(a) : "l"(p));
    return a;
}
__device__ __forceinline__ void cp16(uint32_t dst, const void* src) {
    asm volatile("cp.async.cg.shared.global [%0], [%1], 16;"
                 :: "r"(dst), "l"(src) : "memory");
}
#define CP_COMMIT() asm volatile("cp.async.commit_group;" ::: "memory")
#define CP_WAIT1()  asm volatile("cp.async.wait_group 1;" ::: "memory")

__device__ __forceinline__ void ldsm_x4(uint32_t addr, uint32_t* r) {
    asm volatile("ldmatrix.sync.aligned.m8n8.x4.shared.b16 {%0,%1,%2,%3}, [%4];"
                 : "=r"(r[0]), "=r"(r[1]), "=r"(r[2]), "=r"(r[3]) : "r"(addr));
}
__device__ __forceinline__ void mma_bf16(float* d, const uint32_t* a,
                                         uint32_t b0, uint32_t b1) {
    asm volatile("mma.sync.aligned.m16n8k16.row.col.f32.bf16.bf16.f32 "
                 "{%0,%1,%2,%3}, {%4,%5,%6,%7}, {%8,%9}, {%0,%1,%2,%3};"
                 : "+f"(d[0]), "+f"(d[1]), "+f"(d[2]), "+f"(d[3])
                 : "r"(a[0]), "r"(a[1]), "r"(a[2]), "r"(a[3]),
                   "r"(b0), "r"(b1));
}

// ---------------------------------------------------------------------------
// fp32 -> (hi, lo) bf16 split
// ---------------------------------------------------------------------------
__global__ void __launch_bounds__(256) split_kernel(
    const float* __restrict__ x, __nv_bfloat16* __restrict__ hi,
    __nv_bfloat16* __restrict__ lo, int n)
{
    int i = (blockIdx.x * 256 + threadIdx.x) * 4;
    if (i >= n) return;
    float4 v = *reinterpret_cast<const float4*>(x + i);
    float f[4] = {v.x, v.y, v.z, v.w};
    __nv_bfloat16 h[4], l[4];
#pragma unroll
    for (int j = 0; j < 4; j++) {
        h[j] = __float2bfloat16(f[j]);
        l[j] = __float2bfloat16(f[j] - __bfloat162float(h[j]));
    }
    uint32_t h01 = ((uint32_t)__bfloat16_as_ushort(h[1]) << 16) | __bfloat16_as_ushort(h[0]);
    uint32_t h23 = ((uint32_t)__bfloat16_as_ushort(h[3]) << 16) | __bfloat16_as_ushort(h[2]);
    uint32_t l01 = ((uint32_t)__bfloat16_as_ushort(l[1]) << 16) | __bfloat16_as_ushort(l[0]);
    uint32_t l23 = ((uint32_t)__bfloat16_as_ushort(l[3]) << 16) | __bfloat16_as_ushort(l[2]);
    *reinterpret_cast<uint2*>(hi + i) = make_uint2(h01, h23);
    *reinterpret_cast<uint2*>(lo + i) = make_uint2(l01, l23);
}

// ---------------------------------------------------------------------------
// mma.sync bf16 GEMM:  C = A @ W^T + bias, hi/lo split (3 HMMAs / product).
// 128x128 block tile, 8 warps (warp tile 32x64), K-chunk 32, cp.async 2-stage.
// Smem row stride 80B (64B data + 16B pad) -> conflict-free ldmatrix.
// ---------------------------------------------------------------------------
constexpr int TILE_B = 128 * 80;     // 10240 bytes per (Ah|Al|Wh|Wl) tile
constexpr int STAGE  = 4 * TILE_B;   // 40960
constexpr int GEMM_SMEM = 2 * STAGE; // 81920
constexpr int NC = GK / 32;          // 32 chunks

template <bool HEAD>
__global__ void __launch_bounds__(256, 1) gemm_mma(
    const __nv_bfloat16* __restrict__ Ah, const __nv_bfloat16* __restrict__ Al,
    const __nv_bfloat16* __restrict__ Wh, const __nv_bfloat16* __restrict__ Wl,
    const float* __restrict__ bias, float* __restrict__ C)
{
    extern __shared__ __align__(128) uint8_t smem[];
    const uint32_t sbase = smem_u32(smem);
    const int tid = threadIdx.x;
    const int lane = tid & 31;
    const int wid = tid >> 5;
    const int warp_m = wid >> 1;       // 0..3  (32-row slices)
    const int warp_n = wid & 1;        // 0..1  (64-col slices)
    const int m0 = blockIdx.y * 128;
    const int n0 = blockIdx.x * 128;

    // global load mapping: 2 threads per row; each thread owns 32B of the
    // 64B row-chunk (two cp16).
    const int lrow = tid >> 1;         // 0..127
    const int lq = tid & 1;            // which 32B half
    const __nv_bfloat16* srcs[4] = {
        Ah + (size_t)(m0 + lrow) * GK + lq * 16,
        Al + (size_t)(m0 + lrow) * GK + lq * 16,
        Wh + (size_t)(n0 + lrow) * GK + lq * 16,
        Wl + (size_t)(n0 + lrow) * GK + lq * 16};
    const uint32_t sdst = sbase + lrow * 80 + lq * 32;

    float acc[2][8][4];
#pragma unroll
    for (int mt = 0; mt < 2; mt++)
#pragma unroll
        for (int nt = 0; nt < 8; nt++)
#pragma unroll
            for (int r = 0; r < 4; r++) acc[mt][nt][r] = 0.f;

    // prefetch chunk 0
    {
#pragma unroll
        for (int t = 0; t < 4; t++) {
            cp16(sdst + t * TILE_B, srcs[t]);
            cp16(sdst + t * TILE_B + 16, srcs[t] + 8);
        }
        CP_COMMIT();
    }

    for (int c = 0; c < NC; c++) {
        if (c + 1 < NC) {
            const uint32_t st = ((c + 1) & 1) * STAGE;
#pragma unroll
            for (int t = 0; t < 4; t++) {
                cp16(sdst + st + t * TILE_B, srcs[t] + (c + 1) * 32);
                cp16(sdst + st + t * TILE_B + 16, srcs[t] + (c + 1) * 32 + 8);
            }
        }
        CP_COMMIT();
        CP_WAIT1();
        __syncthreads();

        const uint32_t st = sbase + (c & 1) * STAGE;
#pragma unroll
        for (int k16 = 0; k16 < 2; k16++) {
            // A fragments (hi + lo), 2 m-tiles
            uint32_t ah[2][4], al[2][4];
            const uint32_t a_base =
                st + (warp_m * 32 + (lane & 15)) * 80 + ((lane >> 4) * 16) + k16 * 32;
#pragma unroll
            for (int mt = 0; mt < 2; mt++) {
                ldsm_x4(a_base + mt * 16 * 80, ah[mt]);
                ldsm_x4(a_base + TILE_B + mt * 16 * 80, al[mt]);
            }
            // B fragments: 4 n-tile-pairs
            const int bg = lane >> 3;
            const uint32_t b_base =
                st + 2 * TILE_B +
                (warp_n * 64 + (bg >> 1) * 8 + (lane & 7)) * 80 +
                ((bg & 1) * 16) + k16 * 32;
#pragma unroll
            for (int ntp = 0; ntp < 4; ntp++) {
                uint32_t bh[4], bl[4];
                ldsm_x4(b_base + ntp * 16 * 80, bh);
                ldsm_x4(b_base + TILE_B + ntp * 16 * 80, bl);
#pragma unroll
                for (int half = 0; half < 2; half++) {
                    const int nt = ntp * 2 + half;
#pragma unroll
                    for (int mt = 0; mt < 2; mt++) {
                        mma_bf16(acc[mt][nt], ah[mt], bh[half * 2], bh[half * 2 + 1]);
                        mma_bf16(acc[mt][nt], ah[mt], bl[half * 2], bl[half * 2 + 1]);
                        mma_bf16(acc[mt][nt], al[mt], bh[half * 2], bh[half * 2 + 1]);
                    }
                }
            }
        }
        __syncthreads();
    }

    // epilogue: +bias, scatter
#pragma unroll
    for (int mt = 0; mt < 2; mt++) {
#pragma unroll
        for (int nt = 0; nt < 8; nt++) {
            const int colg = n0 + warp_n * 64 + nt * 8 + (lane & 3) * 2;
            const float2 bv = *reinterpret_cast<const float2*>(&bias[colg]);
#pragma unroll
            for (int half = 0; half < 2; half++) {
                const int rowg = m0 + warp_m * 32 + mt * 16 + (lane >> 2) + half * 8;
                float2 o;
                o.x = acc[mt][nt][half * 2 + 0] + bv.x;
                o.y = acc[mt][nt][half * 2 + 1] + bv.y;
                if (HEAD) {
                    const int b = rowg >> 11, s = rowg & 2047;
                    const int h = colg >> 6, d = colg & 63;
                    float* p = C + ((((size_t)b * NHEAD + h) * SEQ + s) * DHEAD + d);
                    *reinterpret_cast<float2*>(p) = o;
                } else {
                    *reinterpret_cast<float2*>(&C[(size_t)rowg * GN + colg]) = o;
                }
            }
        }
    }
}

// ---------------------------------------------------------------------------
// Flash attention (causal), unchanged (626us, fp32 SIMT).
// ---------------------------------------------------------------------------
__global__ void __launch_bounds__(256) attn_kernel(
    const float* __restrict__ Q, const float* __restrict__ K,
    const float* __restrict__ V, float* __restrict__ O)
{
    extern __shared__ float sm[];
    float* Qs = sm;
    float* Ks = sm + 64 * 68;
    float* Vs = sm + 2 * 64 * 68;
    float* Ps = sm + 3 * 64 * 68;

    const int tid = threadIdx.x;
    const int tx = tid & 15;
    const int ty = tid >> 4;
    const int q0 = ty * 4;
    const int c0 = tx * 4;
    const int bh = blockIdx.y;
    const int qb = blockIdx.x;
    const size_t base = (size_t)bh * SEQ * DHEAD;

#pragma unroll
    for (int it = 0; it < 16; it++) {
        const int e = tid + it * 256;
        const int r = e >> 6, d = e & 63;
        Qs[d * 68 + r] = Q[base + (size_t)(qb * 64 + r) * DHEAD + d];
    }

    float m_i[4], l_i[4], acc[4][4];
#pragma unroll
    for (int i = 0; i < 4; i++) {
        m_i[i] = -1e30f; l_i[i] = 0.f;
#pragma unroll
        for (int j = 0; j < 4; j++) acc[i][j] = 0.f;
    }

    for (int kb = 0; kb <= qb; kb++) {
        __syncthreads();
#pragma unroll
        for (int it = 0; it < 16; it++) {
            const int e = tid + it * 256;
            const int r = e >> 6, d = e & 63;
            const size_t g = base + (size_t)(kb * 64 + r) * DHEAD + d;
            Ks[d * 68 + r] = K[g];
            Vs[r * 68 + d] = V[g];
        }
        __syncthreads();

        float s[4][4];
#pragma unroll
        for (int i = 0; i < 4; i++)
#pragma unroll
            for (int j = 0; j < 4; j++) s[i][j] = 0.f;

#pragma unroll 8
        for (int d = 0; d < 64; d++) {
            float qr[4], kr[4];
            *reinterpret_cast<float4*>(qr) = *reinterpret_cast<const float4*>(&Qs[d * 68 + q0]);
            *reinterpret_cast<float4*>(kr) = *reinterpret_cast<const float4*>(&Ks[d * 68 + c0]);
#pragma unroll
            for (int i = 0; i < 4; i++)
#pragma unroll
                for (int j = 0; j < 4; j++) s[i][j] += qr[i] * kr[j];
        }

        const float scale = 0.125f;
        const bool diag = (kb == qb);
#pragma unroll
        for (int i = 0; i < 4; i++)
#pragma unroll
            for (int j = 0; j < 4; j++) {
                s[i][j] *= scale;
                if (diag && (c0 + j > q0 + i)) s[i][j] = -1e30f;
            }

        float mloc[4];
#pragma unroll
        for (int i = 0; i < 4; i++)
            mloc[i] = fmaxf(fmaxf(s[i][0], s[i][1]), fmaxf(s[i][2], s[i][3]));
#pragma unroll
        for (int off = 1; off < 16; off <<= 1)
#pragma unroll
            for (int i = 0; i < 4; i++)
                mloc[i] = fmaxf(mloc[i], __shfl_xor_sync(0xffffffffu, mloc[i], off));

        float alpha[4];
#pragma unroll
        for (int i = 0; i < 4; i++) {
            const float mn = fmaxf(m_i[i], mloc[i]);
            alpha[i] = __expf(m_i[i] - mn);
            m_i[i] = mn;
        }

        float rs[4];
#pragma unroll
        for (int i = 0; i < 4; i++) {
            float r = 0.f;
#pragma unroll
            for (int j = 0; j < 4; j++) {
                s[i][j] = __expf(s[i][j] - m_i[i]);
                r += s[i][j];
            }
            rs[i] = r;
        }
#pragma unroll
        for (int off = 1; off < 16; off <<= 1)
#pragma unroll
            for (int i = 0; i < 4; i++)
                rs[i] += __shfl_xor_sync(0xffffffffu, rs[i], off);
#pragma unroll
        for (int i = 0; i < 4; i++) {
            l_i[i] = l_i[i] * alpha[i] + rs[i];
#pragma unroll
            for (int j = 0; j < 4; j++) acc[i][j] *= alpha[i];
        }

#pragma unroll
        for (int j = 0; j < 4; j++) {
            float4 pv = make_float4(s[0][j], s[1][j], s[2][j], s[3][j]);
            *reinterpret_cast<float4*>(&Ps[(c0 + j) * 68 + q0]) = pv;
        }
        __syncthreads();

#pragma unroll 8
        for (int k = 0; k < 64; k++) {
            float pr[4], vr[4];
            *reinterpret_cast<float4*>(pr) = *reinterpret_cast<const float4*>(&Ps[k * 68 + q0]);
            *reinterpret_cast<float4*>(vr) = *reinterpret_cast<const float4*>(&Vs[k * 68 + c0]);
#pragma unroll
            for (int i = 0; i < 4; i++)
#pragma unroll
                for (int j = 0; j < 4; j++) acc[i][j] += pr[i] * vr[j];
        }
    }

    const int b = bh / NHEAD, h = bh % NHEAD;
#pragma unroll
    for (int i = 0; i < 4; i++) {
        const float inv = 1.f / l_i[i];
        const int srow = qb * 64 + q0 + i;
        float* orow = O + ((size_t)b * SEQ + srow) * DMODEL + h * DHEAD;
#pragma unroll
        for (int j = 0; j < 4; j++) orow[c0 + j] = acc[i][j] * inv;
    }
}

// ---------------------------------------------------------------------------
extern "C" void kernel_launch(void* const* d_in, const int* in_sizes, int n_in,
                              void* d_out, int out_size)
{
    const float* q   = (const float*)d_in[0];
    const float* k   = (const float*)d_in[1];
    const float* v   = (const float*)d_in[2];
    const float* w_q = (const float*)d_in[4];
    const float* b_q = (const float*)d_in[5];
    const float* w_k = (const float*)d_in[6];
    const float* b_k = (const float*)d_in[7];
    const float* w_v = (const float*)d_in[8];
    const float* b_v = (const float*)d_in[9];
    const float* w_o = (const float*)d_in[10];
    const float* b_o = (const float*)d_in[11];
    float* out = (float*)d_out;

    float *gq, *gk, *gv, *gctx;
    __nv_bfloat16 *ah, *al, *wh, *wl, *ch, *cl;
    cudaGetSymbolAddress((void**)&gq,   g_q);
    cudaGetSymbolAddress((void**)&gk,   g_k);
    cudaGetSymbolAddress((void**)&gv,   g_v);
    cudaGetSymbolAddress((void**)&gctx, g_ctx);
    cudaGetSymbolAddress((void**)&ah,   g_ah);
    cudaGetSymbolAddress((void**)&al,   g_al);
    cudaGetSymbolAddress((void**)&wh,   g_wh);
    cudaGetSymbolAddress((void**)&wl,   g_wl);
    cudaGetSymbolAddress((void**)&ch,   g_ch);
    cudaGetSymbolAddress((void**)&cl,   g_cl);

    static bool attr_set = false;
    if (!attr_set) {
        cudaFuncSetAttribute(gemm_mma<true>,
                             cudaFuncAttributeMaxDynamicSharedMemorySize, GEMM_SMEM);
        cudaFuncSetAttribute(gemm_mma<false>,
                             cudaFuncAttributeMaxDynamicSharedMemorySize, GEMM_SMEM);
        cudaFuncSetAttribute(attn_kernel,
                             cudaFuncAttributeMaxDynamicSharedMemorySize,
                             4 * 64 * 68 * (int)sizeof(float));
        attr_set = true;
    }

    const int nX = GM * GK;            // 4M elems
    const int nW = GN * GK;            // 1M elems
    const float* xs[3] = {q, k, v};
    const float* ws[4] = {w_q, w_k, w_v, w_o};
    for (int i = 0; i < 3; i++)
        split_kernel<<<nX / 1024, 256>>>(xs[i], ah + (size_t)i * nX, al + (size_t)i * nX, nX);
    for (int i = 0; i < 4; i++)
        split_kernel<<<nW / 1024, 256>>>(ws[i], wh + (size_t)i * nW, wl + (size_t)i * nW, nW);

    const dim3 gG(GN / 128, GM / 128);   // (8, 32)
    gemm_mma<true><<<gG, 256, GEMM_SMEM>>>(ah + 0 * (size_t)nX, al + 0 * (size_t)nX,
                                           wh + 0 * (size_t)nW, wl + 0 * (size_t)nW, b_q, gq);
    gemm_mma<true><<<gG, 256, GEMM_SMEM>>>(ah + 1 * (size_t)nX, al + 1 * (size_t)nX,
                                           wh + 1 * (size_t)nW, wl + 1 * (size_t)nW, b_k, gk);
    gemm_mma<true><<<gG, 256, GEMM_SMEM>>>(ah + 2 * (size_t)nX, al + 2 * (size_t)nX,
                                           wh + 2 * (size_t)nW, wl + 2 * (size_t)nW, b_v, gv);

    const int asmem = 4 * 64 * 68 * sizeof(float);
    attn_kernel<<<dim3(SEQ / 64, BSZ * NHEAD), 256, asmem>>>(gq, gk, gv, gctx);

    split_kernel<<<nX / 1024, 256>>>(gctx, ch, cl, nX);
    gemm_mma<false><<<gG, 256, GEMM_SMEM>>>(ch, cl,
                                            wh + 3 * (size_t)nW, wl + 3 * (size_t)nW, b_o, out);
}

// round 7
// speedup vs baseline: 2.5620x; 1.6731x over previous
#include <cuda_runtime.h>
#include <cuda_bf16.h>
#include <cstdint>

#define BSZ 2
#define SEQ 2048
#define DMODEL 1024
#define NHEAD 16
#define DHEAD 64

constexpr int GM = BSZ * SEQ;     // 4096
constexpr int GN = DMODEL;        // 1024
constexpr int GK = DMODEL;        // 1024

// ---------------- scratch (allocation-free device globals) ----------------
__device__ __nv_bfloat16 g_ah[3][GM * GK];   // q,k,v inputs hi (GEMM A)
__device__ __nv_bfloat16 g_al[3][GM * GK];   // lo
__device__ __nv_bfloat16 g_wh[4][GN * GK];   // w_q,w_k,w_v,w_o hi
__device__ __nv_bfloat16 g_wl[4][GN * GK];   // lo
// head-layout projected tensors [B,H,S,DK], hi/lo
__device__ __nv_bfloat16 g_qh[BSZ * NHEAD * SEQ * DHEAD];
__device__ __nv_bfloat16 g_ql[BSZ * NHEAD * SEQ * DHEAD];
__device__ __nv_bfloat16 g_kh2[BSZ * NHEAD * SEQ * DHEAD];
__device__ __nv_bfloat16 g_kl2[BSZ * NHEAD * SEQ * DHEAD];
__device__ __nv_bfloat16 g_vh2[BSZ * NHEAD * SEQ * DHEAD];
__device__ __nv_bfloat16 g_vl2[BSZ * NHEAD * SEQ * DHEAD];
// attention context [B*S, DMODEL] hi/lo (o-proj A operand)
__device__ __nv_bfloat16 g_ch[GM * GK];
__device__ __nv_bfloat16 g_cl[GM * GK];

// ---------------------------- PTX helpers ---------------------------------
__device__ __forceinline__ uint32_t smem_u32(const void* p) {
    uint32_t a;
    asm("{ .reg .u64 t; cvta.to.shared.u64 t, %1; cvt.u32.u64 %0, t; }"
        : "=r"(a) : "l"(p));
    return a;
}
__device__ __forceinline__ void cp16(uint32_t dst, const void* src) {
    asm volatile("cp.async.cg.shared.global [%0], [%1], 16;"
                 :: "r"(dst), "l"(src) : "memory");
}
#define CP_COMMIT() asm volatile("cp.async.commit_group;" ::: "memory")
#define CP_WAIT1()  asm volatile("cp.async.wait_group 1;" ::: "memory")

__device__ __forceinline__ void ldsm_x4(uint32_t addr, uint32_t* r) {
    asm volatile("ldmatrix.sync.aligned.m8n8.x4.shared.b16 {%0,%1,%2,%3}, [%4];"
                 : "=r"(r[0]), "=r"(r[1]), "=r"(r[2]), "=r"(r[3]) : "r"(addr));
}
__device__ __forceinline__ void ldsm_x4_t(uint32_t addr, uint32_t* r) {
    asm volatile("ldmatrix.sync.aligned.m8n8.x4.trans.shared.b16 {%0,%1,%2,%3}, [%4];"
                 : "=r"(r[0]), "=r"(r[1]), "=r"(r[2]), "=r"(r[3]) : "r"(addr));
}
__device__ __forceinline__ void mma_bf16(float* d, const uint32_t* a,
                                         uint32_t b0, uint32_t b1) {
    asm volatile("mma.sync.aligned.m16n8k16.row.col.f32.bf16.bf16.f32 "
                 "{%0,%1,%2,%3}, {%4,%5,%6,%7}, {%8,%9}, {%0,%1,%2,%3};"
                 : "+f"(d[0]), "+f"(d[1]), "+f"(d[2]), "+f"(d[3])
                 : "r"(a[0]), "r"(a[1]), "r"(a[2]), "r"(a[3]),
                   "r"(b0), "r"(b1));
}
// split two floats into packed bf16x2 hi and lo words
__device__ __forceinline__ void split2(float a, float b, uint32_t& hi, uint32_t& lo) {
    __nv_bfloat16 ha = __float2bfloat16(a), hb = __float2bfloat16(b);
    __nv_bfloat16 la = __float2bfloat16(a - __bfloat162float(ha));
    __nv_bfloat16 lb = __float2bfloat16(b - __bfloat162float(hb));
    hi = ((uint32_t)__bfloat16_as_ushort(hb) << 16) | __bfloat16_as_ushort(ha);
    lo = ((uint32_t)__bfloat16_as_ushort(lb) << 16) | __bfloat16_as_ushort(la);
}

// ---------------------------------------------------------------------------
// fp32 -> (hi, lo) bf16 split
// ---------------------------------------------------------------------------
__global__ void __launch_bounds__(256) split_kernel(
    const float* __restrict__ x, __nv_bfloat16* __restrict__ hi,
    __nv_bfloat16* __restrict__ lo, int n)
{
    int i = (blockIdx.x * 256 + threadIdx.x) * 4;
    if (i >= n) return;
    float4 v = *reinterpret_cast<const float4*>(x + i);
    uint32_t h01, h23, l01, l23;
    split2(v.x, v.y, h01, l01);
    split2(v.z, v.w, h23, l23);
    *reinterpret_cast<uint2*>(hi + i) = make_uint2(h01, h23);
    *reinterpret_cast<uint2*>(lo + i) = make_uint2(l01, l23);
}

// ---------------------------------------------------------------------------
// mma.sync bf16 GEMM:  C = A @ W^T + bias, hi/lo split (3 HMMAs / product).
// MODE 0: fp32 output row-major [GM,GN].
// MODE 1: bf16 hi/lo output in head layout [B,H,S,DK].
// ---------------------------------------------------------------------------
constexpr int TILE_B = 128 * 80;     // 10240 bytes per (Ah|Al|Wh|Wl) tile
constexpr int STAGE  = 4 * TILE_B;   // 40960
constexpr int GEMM_SMEM = 2 * STAGE; // 81920
constexpr int NC = GK / 32;          // 32 chunks

template <int MODE>
__global__ void __launch_bounds__(256, 1) gemm_mma(
    const __nv_bfloat16* __restrict__ Ah, const __nv_bfloat16* __restrict__ Al,
    const __nv_bfloat16* __restrict__ Wh, const __nv_bfloat16* __restrict__ Wl,
    const float* __restrict__ bias, float* __restrict__ C,
    __nv_bfloat16* __restrict__ Ch, __nv_bfloat16* __restrict__ Cl)
{
    extern __shared__ __align__(128) uint8_t smem[];
    const uint32_t sbase = smem_u32(smem);
    const int tid = threadIdx.x;
    const int lane = tid & 31;
    const int wid = tid >> 5;
    const int warp_m = wid >> 1;
    const int warp_n = wid & 1;
    const int m0 = blockIdx.y * 128;
    const int n0 = blockIdx.x * 128;

    const int lrow = tid >> 1;
    const int lq = tid & 1;
    const __nv_bfloat16* srcs[4] = {
        Ah + (size_t)(m0 + lrow) * GK + lq * 16,
        Al + (size_t)(m0 + lrow) * GK + lq * 16,
        Wh + (size_t)(n0 + lrow) * GK + lq * 16,
        Wl + (size_t)(n0 + lrow) * GK + lq * 16};
    const uint32_t sdst = sbase + lrow * 80 + lq * 32;

    float acc[2][8][4];
#pragma unroll
    for (int mt = 0; mt < 2; mt++)
#pragma unroll
        for (int nt = 0; nt < 8; nt++)
#pragma unroll
            for (int r = 0; r < 4; r++) acc[mt][nt][r] = 0.f;

    {
#pragma unroll
        for (int t = 0; t < 4; t++) {
            cp16(sdst + t * TILE_B, srcs[t]);
            cp16(sdst + t * TILE_B + 16, srcs[t] + 8);
        }
        CP_COMMIT();
    }

    for (int c = 0; c < NC; c++) {
        if (c + 1 < NC) {
            const uint32_t st = ((c + 1) & 1) * STAGE;
#pragma unroll
            for (int t = 0; t < 4; t++) {
                cp16(sdst + st + t * TILE_B, srcs[t] + (c + 1) * 32);
                cp16(sdst + st + t * TILE_B + 16, srcs[t] + (c + 1) * 32 + 8);
            }
        }
        CP_COMMIT();
        CP_WAIT1();
        __syncthreads();

        const uint32_t st = sbase + (c & 1) * STAGE;
#pragma unroll
        for (int k16 = 0; k16 < 2; k16++) {
            uint32_t ah[2][4], al[2][4];
            const uint32_t a_base =
                st + (warp_m * 32 + (lane & 15)) * 80 + ((lane >> 4) * 16) + k16 * 32;
#pragma unroll
            for (int mt = 0; mt < 2; mt++) {
                ldsm_x4(a_base + mt * 16 * 80, ah[mt]);
                ldsm_x4(a_base + TILE_B + mt * 16 * 80, al[mt]);
            }
            const int bg = lane >> 3;
            const uint32_t b_base =
                st + 2 * TILE_B +
                (warp_n * 64 + (bg >> 1) * 8 + (lane & 7)) * 80 +
                ((bg & 1) * 16) + k16 * 32;
#pragma unroll
            for (int ntp = 0; ntp < 4; ntp++) {
                uint32_t bh[4], bl[4];
                ldsm_x4(b_base + ntp * 16 * 80, bh);
                ldsm_x4(b_base + TILE_B + ntp * 16 * 80, bl);
#pragma unroll
                for (int half = 0; half < 2; half++) {
                    const int nt = ntp * 2 + half;
#pragma unroll
                    for (int mt = 0; mt < 2; mt++) {
                        mma_bf16(acc[mt][nt], ah[mt], bh[half * 2], bh[half * 2 + 1]);
                        mma_bf16(acc[mt][nt], ah[mt], bl[half * 2], bl[half * 2 + 1]);
                        mma_bf16(acc[mt][nt], al[mt], bh[half * 2], bh[half * 2 + 1]);
                    }
                }
            }
        }
        __syncthreads();
    }

#pragma unroll
    for (int mt = 0; mt < 2; mt++) {
#pragma unroll
        for (int nt = 0; nt < 8; nt++) {
            const int colg = n0 + warp_n * 64 + nt * 8 + (lane & 3) * 2;
            const float2 bv = *reinterpret_cast<const float2*>(&bias[colg]);
#pragma unroll
            for (int half = 0; half < 2; half++) {
                const int rowg = m0 + warp_m * 32 + mt * 16 + (lane >> 2) + half * 8;
                const float ox = acc[mt][nt][half * 2 + 0] + bv.x;
                const float oy = acc[mt][nt][half * 2 + 1] + bv.y;
                if (MODE == 1) {
                    const int b = rowg >> 11, s = rowg & 2047;
                    const int h = colg >> 6, d = colg & 63;
                    const size_t idx = (((size_t)b * NHEAD + h) * SEQ + s) * DHEAD + d;
                    uint32_t hi, lo;
                    split2(ox, oy, hi, lo);
                    *reinterpret_cast<uint32_t*>(Ch + idx) = hi;
                    *reinterpret_cast<uint32_t*>(Cl + idx) = lo;
                } else {
                    float2 o; o.x = ox; o.y = oy;
                    *reinterpret_cast<float2*>(&C[(size_t)rowg * GN + colg]) = o;
                }
            }
        }
    }
}

// ---------------------------------------------------------------------------
// Tensor-core flash attention (causal), bf16 hi/lo mma.sync.
// CTA: 128 q-rows x DK=64, 8 warps (16 rows each); key blocks of 64,
// cp.async double-buffered K/V hi/lo; 144B padded smem rows.
// Writes ctx [B*S, DMODEL] as bf16 hi/lo.
// ---------------------------------------------------------------------------
constexpr int AQ_BYTES  = 128 * 144;             // 18432 per Q array
constexpr int AKV_BYTES = 64 * 144;              // 9216 per K/V array
constexpr int ASTAGE    = 4 * AKV_BYTES;         // 36864 (Kh,Kl,Vh,Vl)
constexpr int ATT_SMEM  = 2 * AQ_BYTES + 2 * ASTAGE;  // 110592

__global__ void __launch_bounds__(256, 1) attn_mma(
    const __nv_bfloat16* __restrict__ Qh, const __nv_bfloat16* __restrict__ Ql,
    const __nv_bfloat16* __restrict__ Kh, const __nv_bfloat16* __restrict__ Kl,
    const __nv_bfloat16* __restrict__ Vh, const __nv_bfloat16* __restrict__ Vl,
    __nv_bfloat16* __restrict__ Ch, __nv_bfloat16* __restrict__ Cl)
{
    extern __shared__ __align__(128) uint8_t smem[];
    const uint32_t sbase = smem_u32(smem);
    const int tid = threadIdx.x, lane = tid & 31, wm = tid >> 5;
    const int qb = blockIdx.x, bh = blockIdx.y;
    const size_t base = (size_t)bh * SEQ * DHEAD;
    const int nkb = 2 * qb + 2;

    // Q load (joins block-0's cp.async group)
    {
        const int r = tid >> 1, half = tid & 1;
        const size_t g = base + (size_t)(qb * 128 + r) * DHEAD + half * 32;
        const uint32_t d = sbase + r * 144 + half * 64;
#pragma unroll
        for (int i = 0; i < 4; i++) {
            cp16(d + i * 16, Qh + g + i * 8);
            cp16(d + AQ_BYTES + i * 16, Ql + g + i * 8);
        }
    }
    auto loadKV = [&](int kb) {
        const uint32_t ss = sbase + 2 * AQ_BYTES + (kb & 1) * ASTAGE;
        const int r = tid >> 2, seg = tid & 3;
        const size_t g = base + (size_t)(kb * 64 + r) * DHEAD + seg * 16;
        const uint32_t d = ss + r * 144 + seg * 32;
        cp16(d, Kh + g);                      cp16(d + 16, Kh + g + 8);
        cp16(d + AKV_BYTES, Kl + g);          cp16(d + AKV_BYTES + 16, Kl + g + 8);
        cp16(d + 2 * AKV_BYTES, Vh + g);      cp16(d + 2 * AKV_BYTES + 16, Vh + g + 8);
        cp16(d + 3 * AKV_BYTES, Vl + g);      cp16(d + 3 * AKV_BYTES + 16, Vl + g + 8);
    };
    loadKV(0);
    CP_COMMIT();

    float m0 = -1e30f, m1 = -1e30f, l0 = 0.f, l1 = 0.f;
    float acco[8][4];
#pragma unroll
    for (int nt = 0; nt < 8; nt++)
#pragma unroll
        for (int e = 0; e < 4; e++) acco[nt][e] = 0.f;

    const int bg = lane >> 3;
    const uint32_t aq = sbase + (wm * 16 + (lane & 15)) * 144 + (lane >> 4) * 16;

    for (int kb = 0; kb < nkb; kb++) {
        if (kb + 1 < nkb) loadKV(kb + 1);
        CP_COMMIT();
        CP_WAIT1();
        __syncthreads();
        const uint32_t ss = sbase + 2 * AQ_BYTES + (kb & 1) * ASTAGE;

        // ---- S = Q K^T (hi/lo 3-mma) ----
        float accs[8][4];
#pragma unroll
        for (int nt = 0; nt < 8; nt++)
#pragma unroll
            for (int e = 0; e < 4; e++) accs[nt][e] = 0.f;

        const uint32_t kbase = ss + ((bg >> 1) * 8 + (lane & 7)) * 144 + (bg & 1) * 16;
#pragma unroll
        for (int kc = 0; kc < 4; kc++) {
            uint32_t qh4[4], ql4[4];
            ldsm_x4(aq + kc * 32, qh4);
            ldsm_x4(aq + AQ_BYTES + kc * 32, ql4);
#pragma unroll
            for (int ntp = 0; ntp < 4; ntp++) {
                uint32_t kh4[4], kl4[4];
                ldsm_x4(kbase + ntp * 16 * 144 + kc * 32, kh4);
                ldsm_x4(kbase + AKV_BYTES + ntp * 16 * 144 + kc * 32, kl4);
#pragma unroll
                for (int hf = 0; hf < 2; hf++) {
                    const int nt = ntp * 2 + hf;
                    mma_bf16(accs[nt], qh4, kh4[hf * 2], kh4[hf * 2 + 1]);
                    mma_bf16(accs[nt], qh4, kl4[hf * 2], kl4[hf * 2 + 1]);
                    mma_bf16(accs[nt], ql4, kh4[hf * 2], kh4[hf * 2 + 1]);
                }
            }
        }

        // ---- online softmax (rows r0 = ..+lane>>2 and r0+8) ----
        const int r0 = qb * 128 + wm * 16 + (lane >> 2);
        const bool needMask = (kb * 64 + 63 > qb * 128 + wm * 16);
        float mx0 = -1e30f, mx1 = -1e30f;
#pragma unroll
        for (int nt = 0; nt < 8; nt++) {
#pragma unroll
            for (int e = 0; e < 4; e++) {
                float s = accs[nt][e] * 0.125f;
                if (needMask) {
                    const int col = kb * 64 + nt * 8 + (lane & 3) * 2 + (e & 1);
                    const int row = r0 + (e >> 1) * 8;
                    if (col > row) s = -1e30f;
                }
                accs[nt][e] = s;
            }
            mx0 = fmaxf(mx0, fmaxf(accs[nt][0], accs[nt][1]));
            mx1 = fmaxf(mx1, fmaxf(accs[nt][2], accs[nt][3]));
        }
        mx0 = fmaxf(mx0, __shfl_xor_sync(0xffffffffu, mx0, 1));
        mx0 = fmaxf(mx0, __shfl_xor_sync(0xffffffffu, mx0, 2));
        mx1 = fmaxf(mx1, __shfl_xor_sync(0xffffffffu, mx1, 1));
        mx1 = fmaxf(mx1, __shfl_xor_sync(0xffffffffu, mx1, 2));
        const float mn0 = fmaxf(m0, mx0), mn1 = fmaxf(m1, mx1);
        const float al0 = __expf(m0 - mn0), al1 = __expf(m1 - mn1);
        float rs0 = 0.f, rs1 = 0.f;
#pragma unroll
        for (int nt = 0; nt < 8; nt++) {
            accs[nt][0] = __expf(accs[nt][0] - mn0);
            accs[nt][1] = __expf(accs[nt][1] - mn0);
            accs[nt][2] = __expf(accs[nt][2] - mn1);
            accs[nt][3] = __expf(accs[nt][3] - mn1);
            rs0 += accs[nt][0] + accs[nt][1];
            rs1 += accs[nt][2] + accs[nt][3];
        }
        rs0 += __shfl_xor_sync(0xffffffffu, rs0, 1);
        rs0 += __shfl_xor_sync(0xffffffffu, rs0, 2);
        rs1 += __shfl_xor_sync(0xffffffffu, rs1, 1);
        rs1 += __shfl_xor_sync(0xffffffffu, rs1, 2);
        l0 = l0 * al0 + rs0; l1 = l1 * al1 + rs1;
        m0 = mn0; m1 = mn1;
#pragma unroll
        for (int nt = 0; nt < 8; nt++) {
            acco[nt][0] *= al0; acco[nt][1] *= al0;
            acco[nt][2] *= al1; acco[nt][3] *= al1;
        }

        // ---- O += P V (hi/lo 3-mma), P from registers ----
#pragma unroll
        for (int c = 0; c < 4; c++) {
            uint32_t pah[4], pal[4];
            split2(accs[2 * c][0], accs[2 * c][1], pah[0], pal[0]);
            split2(accs[2 * c][2], accs[2 * c][3], pah[1], pal[1]);
            split2(accs[2 * c + 1][0], accs[2 * c + 1][1], pah[2], pal[2]);
            split2(accs[2 * c + 1][2], accs[2 * c + 1][3], pah[3], pal[3]);
            const uint32_t vb = ss + 2 * AKV_BYTES +
                (c * 16 + (bg & 1) * 8 + (lane & 7)) * 144 + (bg >> 1) * 16;
#pragma unroll
            for (int dp = 0; dp < 4; dp++) {
                uint32_t vh4[4], vl4[4];
                ldsm_x4_t(vb + dp * 32, vh4);
                ldsm_x4_t(vb + AKV_BYTES + dp * 32, vl4);
#pragma unroll
                for (int hf = 0; hf < 2; hf++) {
                    const int nt = dp * 2 + hf;
                    mma_bf16(acco[nt], pah, vh4[hf * 2], vh4[hf * 2 + 1]);
                    mma_bf16(acco[nt], pah, vl4[hf * 2], vl4[hf * 2 + 1]);
                    mma_bf16(acco[nt], pal, vh4[hf * 2], vh4[hf * 2 + 1]);
                }
            }
        }
        __syncthreads();
    }

    // ---- epilogue: normalize, write ctx bf16 hi/lo ----
    const int b = bh >> 4, h = bh & 15;
    const float i0 = 1.f / l0, i1 = 1.f / l1;
    const size_t tok = (size_t)b * SEQ + qb * 128 + wm * 16 + (lane >> 2);
#pragma unroll
    for (int nt = 0; nt < 8; nt++) {
        const int d0 = h * DHEAD + nt * 8 + (lane & 3) * 2;
        uint32_t hi, lo;
        split2(acco[nt][0] * i0, acco[nt][1] * i0, hi, lo);
        *reinterpret_cast<uint32_t*>(Ch + tok * DMODEL + d0) = hi;
        *reinterpret_cast<uint32_t*>(Cl + tok * DMODEL + d0) = lo;
        split2(acco[nt][2] * i1, acco[nt][3] * i1, hi, lo);
        *reinterpret_cast<uint32_t*>(Ch + (tok + 8) * DMODEL + d0) = hi;
        *reinterpret_cast<uint32_t*>(Cl + (tok + 8) * DMODEL + d0) = lo;
    }
}

// ---------------------------------------------------------------------------
extern "C" void kernel_launch(void* const* d_in, const int* in_sizes, int n_in,
                              void* d_out, int out_size)
{
    const float* q   = (const float*)d_in[0];
    const float* k   = (const float*)d_in[1];
    const float* v   = (const float*)d_in[2];
    const float* w_q = (const float*)d_in[4];
    const float* b_q = (const float*)d_in[5];
    const float* w_k = (const float*)d_in[6];
    const float* b_k = (const float*)d_in[7];
    const float* w_v = (const float*)d_in[8];
    const float* b_v = (const float*)d_in[9];
    const float* w_o = (const float*)d_in[10];
    const float* b_o = (const float*)d_in[11];
    float* out = (float*)d_out;

    __nv_bfloat16 *ah, *al, *wh, *wl, *ch, *cl;
    __nv_bfloat16 *qh, *ql, *kh, *kl, *vh, *vl;
    cudaGetSymbolAddress((void**)&ah, g_ah);
    cudaGetSymbolAddress((void**)&al, g_al);
    cudaGetSymbolAddress((void**)&wh, g_wh);
    cudaGetSymbolAddress((void**)&wl, g_wl);
    cudaGetSymbolAddress((void**)&ch, g_ch);
    cudaGetSymbolAddress((void**)&cl, g_cl);
    cudaGetSymbolAddress((void**)&qh, g_qh);
    cudaGetSymbolAddress((void**)&ql, g_ql);
    cudaGetSymbolAddress((void**)&kh, g_kh2);
    cudaGetSymbolAddress((void**)&kl, g_kl2);
    cudaGetSymbolAddress((void**)&vh, g_vh2);
    cudaGetSymbolAddress((void**)&vl, g_vl2);

    static bool attr_set = false;
    if (!attr_set) {
        cudaFuncSetAttribute(gemm_mma<0>,
                             cudaFuncAttributeMaxDynamicSharedMemorySize, GEMM_SMEM);
        cudaFuncSetAttribute(gemm_mma<1>,
                             cudaFuncAttributeMaxDynamicSharedMemorySize, GEMM_SMEM);
        cudaFuncSetAttribute(attn_mma,
                             cudaFuncAttributeMaxDynamicSharedMemorySize, ATT_SMEM);
        attr_set = true;
    }

    const int nX = GM * GK;
    const int nW = GN * GK;
    const float* xs[3] = {q, k, v};
    const float* ws[4] = {w_q, w_k, w_v, w_o};
    for (int i = 0; i < 3; i++)
        split_kernel<<<nX / 1024, 256>>>(xs[i], ah + (size_t)i * nX, al + (size_t)i * nX, nX);
    for (int i = 0; i < 4; i++)
        split_kernel<<<nW / 1024, 256>>>(ws[i], wh + (size_t)i * nW, wl + (size_t)i * nW, nW);

    const dim3 gG(GN / 128, GM / 128);   // (8, 32)
    gemm_mma<1><<<gG, 256, GEMM_SMEM>>>(ah, al, wh, wl, b_q, nullptr, qh, ql);
    gemm_mma<1><<<gG, 256, GEMM_SMEM>>>(ah + (size_t)nX, al + (size_t)nX,
                                        wh + (size_t)nW, wl + (size_t)nW, b_k, nullptr, kh, kl);
    gemm_mma<1><<<gG, 256, GEMM_SMEM>>>(ah + 2 * (size_t)nX, al + 2 * (size_t)nX,
                                        wh + 2 * (size_t)nW, wl + 2 * (size_t)nW, b_v, nullptr, vh, vl);

    attn_mma<<<dim3(SEQ / 128, BSZ * NHEAD), 256, ATT_SMEM>>>(
        qh, ql, kh, kl, vh, vl, ch, cl);

    gemm_mma<0><<<gG, 256, GEMM_SMEM>>>(ch, cl,
                                        wh + 3 * (size_t)nW, wl + 3 * (size_t)nW, b_o, out,
                                        nullptr, nullptr);
}

// round 10
// speedup vs baseline: 2.6493x; 1.0341x over previous
#include <cuda_runtime.h>
#include <cuda_bf16.h>
#include <cstdint>

#define BSZ 2
#define SEQ 2048
#define DMODEL 1024
#define NHEAD 16
#define DHEAD 64

constexpr int GM = BSZ * SEQ;     // 4096
constexpr int GN = DMODEL;        // 1024
constexpr int GK = DMODEL;        // 1024

// ---------------- scratch (allocation-free device globals) ----------------
__device__ __nv_bfloat16 g_ah[3][GM * GK];   // q,k,v inputs hi (GEMM A)
__device__ __nv_bfloat16 g_al[3][GM * GK];   // lo
__device__ __nv_bfloat16 g_wh[4][GN * GK];   // w_q,w_k,w_v,w_o hi
__device__ __nv_bfloat16 g_wl[4][GN * GK];   // lo
// head-layout projected tensors [B,H,S,DK], hi/lo
__device__ __nv_bfloat16 g_qh[BSZ * NHEAD * SEQ * DHEAD];
__device__ __nv_bfloat16 g_ql[BSZ * NHEAD * SEQ * DHEAD];
__device__ __nv_bfloat16 g_kh2[BSZ * NHEAD * SEQ * DHEAD];
__device__ __nv_bfloat16 g_kl2[BSZ * NHEAD * SEQ * DHEAD];
__device__ __nv_bfloat16 g_vh2[BSZ * NHEAD * SEQ * DHEAD];
__device__ __nv_bfloat16 g_vl2[BSZ * NHEAD * SEQ * DHEAD];
// attention context [B*S, DMODEL] hi/lo (o-proj A operand)
__device__ __nv_bfloat16 g_ch[GM * GK];
__device__ __nv_bfloat16 g_cl[GM * GK];

// ---------------------------- PTX helpers ---------------------------------
__device__ __forceinline__ uint32_t smem_u32(const void* p) {
    uint32_t a;
    asm("{ .reg .u64 t; cvta.to.shared.u64 t, %1; cvt.u32.u64 %0, t; }"
        : "=r"(a) : "l"(p));
    return a;
}
__device__ __forceinline__ void cp16(uint32_t dst, const void* src) {
    asm volatile("cp.async.cg.shared.global [%0], [%1], 16;"
                 :: "r"(dst), "l"(src) : "memory");
}
#define CP_COMMIT() asm volatile("cp.async.commit_group;" ::: "memory")
#define CP_WAIT1()  asm volatile("cp.async.wait_group 1;" ::: "memory")

__device__ __forceinline__ void ldsm_x4(uint32_t addr, uint32_t* r) {
    asm volatile("ldmatrix.sync.aligned.m8n8.x4.shared.b16 {%0,%1,%2,%3}, [%4];"
                 : "=r"(r[0]), "=r"(r[1]), "=r"(r[2]), "=r"(r[3]) : "r"(addr));
}
__device__ __forceinline__ void ldsm_x4_t(uint32_t addr, uint32_t* r) {
    asm volatile("ldmatrix.sync.aligned.m8n8.x4.trans.shared.b16 {%0,%1,%2,%3}, [%4];"
                 : "=r"(r[0]), "=r"(r[1]), "=r"(r[2]), "=r"(r[3]) : "r"(addr));
}
__device__ __forceinline__ void mma_bf16(float* d, const uint32_t* a,
                                         uint32_t b0, uint32_t b1) {
    asm volatile("mma.sync.aligned.m16n8k16.row.col.f32.bf16.bf16.f32 "
                 "{%0,%1,%2,%3}, {%4,%5,%6,%7}, {%8,%9}, {%0,%1,%2,%3};"
                 : "+f"(d[0]), "+f"(d[1]), "+f"(d[2]), "+f"(d[3])
                 : "r"(a[0]), "r"(a[1]), "r"(a[2]), "r"(a[3]),
                   "r"(b0), "r"(b1));
}
// split two floats into packed bf16x2 hi and lo words
__device__ __forceinline__ void split2(float a, float b, uint32_t& hi, uint32_t& lo) {
    __nv_bfloat16 ha = __float2bfloat16(a), hb = __float2bfloat16(b);
    __nv_bfloat16 la = __float2bfloat16(a - __bfloat162float(ha));
    __nv_bfloat16 lb = __float2bfloat16(b - __bfloat162float(hb));
    hi = ((uint32_t)__bfloat16_as_ushort(hb) << 16) | __bfloat16_as_ushort(ha);
    lo = ((uint32_t)__bfloat16_as_ushort(lb) << 16) | __bfloat16_as_ushort(la);
}

// ---------------------------------------------------------------------------
// fused fp32 -> (hi, lo) bf16 split for all 7 tensors in one launch
// segments: 3 x 4M elems (q,k,v), 4 x 1M elems (weights)
// ---------------------------------------------------------------------------
struct SplitArgs {
    const float* src[7];
    __nv_bfloat16* hi[7];
    __nv_bfloat16* lo[7];
};

__global__ void __launch_bounds__(256) split_all_kernel(SplitArgs args)
{
    int b = blockIdx.x;
    int seg, off;
    if (b < 3 * 4096) { seg = b >> 12; off = b & 4095; }
    else { b -= 3 * 4096; seg = 3 + (b >> 10); off = b & 1023; }
    const int i = (off * 256 + threadIdx.x) * 4;
    float4 v = *reinterpret_cast<const float4*>(args.src[seg] + i);
    uint32_t h01, h23, l01, l23;
    split2(v.x, v.y, h01, l01);
    split2(v.z, v.w, h23, l23);
    *reinterpret_cast<uint2*>(args.hi[seg] + i) = make_uint2(h01, h23);
    *reinterpret_cast<uint2*>(args.lo[seg] + i) = make_uint2(l01, l23);
}

// ---------------------------------------------------------------------------
// mma.sync bf16 GEMM:  C = A @ W^T + bias, hi/lo split (3 HMMAs / product).
// MODE 0: fp32 output row-major [GM,GN].
// MODE 1: bf16 hi/lo output in head layout [B,H,S,DK].
// 2 CTAs/SM resident (160KB smem, <=128 regs).
// ---------------------------------------------------------------------------
constexpr int TILE_B = 128 * 80;     // 10240 bytes per (Ah|Al|Wh|Wl) tile
constexpr int STAGE  = 4 * TILE_B;   // 40960
constexpr int GEMM_SMEM = 2 * STAGE; // 81920
constexpr int NC = GK / 32;          // 32 chunks

template <int MODE>
__global__ void __launch_bounds__(256, 2) gemm_mma(
    const __nv_bfloat16* __restrict__ Ah, const __nv_bfloat16* __restrict__ Al,
    const __nv_bfloat16* __restrict__ Wh, const __nv_bfloat16* __restrict__ Wl,
    const float* __restrict__ bias, float* __restrict__ C,
    __nv_bfloat16* __restrict__ Ch, __nv_bfloat16* __restrict__ Cl)
{
    extern __shared__ __align__(128) uint8_t smem[];
    const uint32_t sbase = smem_u32(smem);
    const int tid = threadIdx.x;
    const int lane = tid & 31;
    const int wid = tid >> 5;
    const int warp_m = wid >> 1;
    const int warp_n = wid & 1;
    const int m0 = blockIdx.y * 128;
    const int n0 = blockIdx.x * 128;

    const int lrow = tid >> 1;
    const int lq = tid & 1;
    const __nv_bfloat16* srcs[4] = {
        Ah + (size_t)(m0 + lrow) * GK + lq * 16,
        Al + (size_t)(m0 + lrow) * GK + lq * 16,
        Wh + (size_t)(n0 + lrow) * GK + lq * 16,
        Wl + (size_t)(n0 + lrow) * GK + lq * 16};
    const uint32_t sdst = sbase + lrow * 80 + lq * 32;

    float acc[2][8][4];
#pragma unroll
    for (int mt = 0; mt < 2; mt++)
#pragma unroll
        for (int nt = 0; nt < 8; nt++)
#pragma unroll
            for (int r = 0; r < 4; r++) acc[mt][nt][r] = 0.f;

    {
#pragma unroll
        for (int t = 0; t < 4; t++) {
            cp16(sdst + t * TILE_B, srcs[t]);
            cp16(sdst + t * TILE_B + 16, srcs[t] + 8);
        }
        CP_COMMIT();
    }

    for (int c = 0; c < NC; c++) {
        if (c + 1 < NC) {
            const uint32_t st = ((c + 1) & 1) * STAGE;
#pragma unroll
            for (int t = 0; t < 4; t++) {
                cp16(sdst + st + t * TILE_B, srcs[t] + (c + 1) * 32);
                cp16(sdst + st + t * TILE_B + 16, srcs[t] + (c + 1) * 32 + 8);
            }
        }
        CP_COMMIT();
        CP_WAIT1();
        __syncthreads();

        const uint32_t st = sbase + (c & 1) * STAGE;
#pragma unroll
        for (int k16 = 0; k16 < 2; k16++) {
            uint32_t ah[2][4], al[2][4];
            const uint32_t a_base =
                st + (warp_m * 32 + (lane & 15)) * 80 + ((lane >> 4) * 16) + k16 * 32;
#pragma unroll
            for (int mt = 0; mt < 2; mt++) {
                ldsm_x4(a_base + mt * 16 * 80, ah[mt]);
                ldsm_x4(a_base + TILE_B + mt * 16 * 80, al[mt]);
            }
            const int bg = lane >> 3;
            const uint32_t b_base =
                st + 2 * TILE_B +
                (warp_n * 64 + (bg >> 1) * 8 + (lane & 7)) * 80 +
                ((bg & 1) * 16) + k16 * 32;
#pragma unroll
            for (int ntp = 0; ntp < 4; ntp++) {
                uint32_t bh[4], bl[4];
                ldsm_x4(b_base + ntp * 16 * 80, bh);
                ldsm_x4(b_base + TILE_B + ntp * 16 * 80, bl);
#pragma unroll
                for (int half = 0; half < 2; half++) {
                    const int nt = ntp * 2 + half;
#pragma unroll
                    for (int mt = 0; mt < 2; mt++) {
                        mma_bf16(acc[mt][nt], ah[mt], bh[half * 2], bh[half * 2 + 1]);
                        mma_bf16(acc[mt][nt], ah[mt], bl[half * 2], bl[half * 2 + 1]);
                        mma_bf16(acc[mt][nt], al[mt], bh[half * 2], bh[half * 2 + 1]);
                    }
                }
            }
        }
        __syncthreads();
    }

#pragma unroll
    for (int mt = 0; mt < 2; mt++) {
#pragma unroll
        for (int nt = 0; nt < 8; nt++) {
            const int colg = n0 + warp_n * 64 + nt * 8 + (lane & 3) * 2;
            const float2 bv = *reinterpret_cast<const float2*>(&bias[colg]);
#pragma unroll
            for (int half = 0; half < 2; half++) {
                const int rowg = m0 + warp_m * 32 + mt * 16 + (lane >> 2) + half * 8;
                const float ox = acc[mt][nt][half * 2 + 0] + bv.x;
                const float oy = acc[mt][nt][half * 2 + 1] + bv.y;
                if (MODE == 1) {
                    const int b = rowg >> 11, s = rowg & 2047;
                    const int h = colg >> 6, d = colg & 63;
                    const size_t idx = (((size_t)b * NHEAD + h) * SEQ + s) * DHEAD + d;
                    uint32_t hi, lo;
                    split2(ox, oy, hi, lo);
                    *reinterpret_cast<uint32_t*>(Ch + idx) = hi;
                    *reinterpret_cast<uint32_t*>(Cl + idx) = lo;
                } else {
                    float2 o; o.x = ox; o.y = oy;
                    *reinterpret_cast<float2*>(&C[(size_t)rowg * GN + colg]) = o;
                }
            }
        }
    }
}

// ---------------------------------------------------------------------------
// Tensor-core flash attention (causal), bf16 hi/lo mma.sync.
// CTA: 128 q-rows x DK=64, 8 warps (16 rows each); key blocks of 64,
// cp.async double-buffered K/V hi/lo; 144B padded smem rows.
// Heavy tiles launched first (qb reversed); 2 CTAs/SM target.
// ---------------------------------------------------------------------------
constexpr int AQ_BYTES  = 128 * 144;             // 18432 per Q array
constexpr int AKV_BYTES = 64 * 144;              // 9216 per K/V array
constexpr int ASTAGE    = 4 * AKV_BYTES;         // 36864 (Kh,Kl,Vh,Vl)
constexpr int ATT_SMEM  = 2 * AQ_BYTES + 2 * ASTAGE;  // 110592

__global__ void __launch_bounds__(256, 2) attn_mma(
    const __nv_bfloat16* __restrict__ Qh, const __nv_bfloat16* __restrict__ Ql,
    const __nv_bfloat16* __restrict__ Kh, const __nv_bfloat16* __restrict__ Kl,
    const __nv_bfloat16* __restrict__ Vh, const __nv_bfloat16* __restrict__ Vl,
    __nv_bfloat16* __restrict__ Ch, __nv_bfloat16* __restrict__ Cl)
{
    extern __shared__ __align__(128) uint8_t smem[];
    const uint32_t sbase = smem_u32(smem);
    const int tid = threadIdx.x, lane = tid & 31, wm = tid >> 5;
    const int qb = gridDim.x - 1 - blockIdx.x;   // heavy tiles first
    const int bh = blockIdx.y;
    const size_t base = (size_t)bh * SEQ * DHEAD;
    const int nkb = 2 * qb + 2;

    // Q load (joins block-0's cp.async group)
    {
        const int r = tid >> 1, half = tid & 1;
        const size_t g = base + (size_t)(qb * 128 + r) * DHEAD + half * 32;
        const uint32_t d = sbase + r * 144 + half * 64;
#pragma unroll
        for (int i = 0; i < 4; i++) {
            cp16(d + i * 16, Qh + g + i * 8);
            cp16(d + AQ_BYTES + i * 16, Ql + g + i * 8);
        }
    }
    auto loadKV = [&](int kb) {
        const uint32_t ss = sbase + 2 * AQ_BYTES + (kb & 1) * ASTAGE;
        const int r = tid >> 2, seg = tid & 3;
        const size_t g = base + (size_t)(kb * 64 + r) * DHEAD + seg * 16;
        const uint32_t d = ss + r * 144 + seg * 32;
        cp16(d, Kh + g);                      cp16(d + 16, Kh + g + 8);
        cp16(d + AKV_BYTES, Kl + g);          cp16(d + AKV_BYTES + 16, Kl + g + 8);
        cp16(d + 2 * AKV_BYTES, Vh + g);      cp16(d + 2 * AKV_BYTES + 16, Vh + g + 8);
        cp16(d + 3 * AKV_BYTES, Vl + g);      cp16(d + 3 * AKV_BYTES + 16, Vl + g + 8);
    };
    loadKV(0);
    CP_COMMIT();

    float m0 = -1e30f, m1 = -1e30f, l0 = 0.f, l1 = 0.f;
    float acco[8][4];
#pragma unroll
    for (int nt = 0; nt < 8; nt++)
#pragma unroll
        for (int e = 0; e < 4; e++) acco[nt][e] = 0.f;

    const int bg = lane >> 3;
    const uint32_t aq = sbase + (wm * 16 + (lane & 15)) * 144 + (lane >> 4) * 16;

    for (int kb = 0; kb < nkb; kb++) {
        if (kb + 1 < nkb) loadKV(kb + 1);
        CP_COMMIT();
        CP_WAIT1();
        __syncthreads();
        const uint32_t ss = sbase + 2 * AQ_BYTES + (kb & 1) * ASTAGE;

        // ---- S = Q K^T (hi/lo 3-mma) ----
        float accs[8][4];
#pragma unroll
        for (int nt = 0; nt < 8; nt++)
#pragma unroll
            for (int e = 0; e < 4; e++) accs[nt][e] = 0.f;

        const uint32_t kbase = ss + ((bg >> 1) * 8 + (lane & 7)) * 144 + (bg & 1) * 16;
#pragma unroll
        for (int kc = 0; kc < 4; kc++) {
            uint32_t qh4[4], ql4[4];
            ldsm_x4(aq + kc * 32, qh4);
            ldsm_x4(aq + AQ_BYTES + kc * 32, ql4);
#pragma unroll
            for (int ntp = 0; ntp < 4; ntp++) {
                uint32_t kh4[4], kl4[4];
                ldsm_x4(kbase + ntp * 16 * 144 + kc * 32, kh4);
                ldsm_x4(kbase + AKV_BYTES + ntp * 16 * 144 + kc * 32, kl4);
#pragma unroll
                for (int hf = 0; hf < 2; hf++) {
                    const int nt = ntp * 2 + hf;
                    mma_bf16(accs[nt], qh4, kh4[hf * 2], kh4[hf * 2 + 1]);
                    mma_bf16(accs[nt], qh4, kl4[hf * 2], kl4[hf * 2 + 1]);
                    mma_bf16(accs[nt], ql4, kh4[hf * 2], kh4[hf * 2 + 1]);
                }
            }
        }

        // ---- online softmax (rows r0 = ..+lane>>2 and r0+8) ----
        const int r0 = qb * 128 + wm * 16 + (lane >> 2);
        const bool needMask = (kb * 64 + 63 > qb * 128 + wm * 16);
        float mx0 = -1e30f, mx1 = -1e30f;
#pragma unroll
        for (int nt = 0; nt < 8; nt++) {
#pragma unroll
            for (int e = 0; e < 4; e++) {
                float s = accs[nt][e] * 0.125f;
                if (needMask) {
                    const int col = kb * 64 + nt * 8 + (lane & 3) * 2 + (e & 1);
                    const int row = r0 + (e >> 1) * 8;
                    if (col > row) s = -1e30f;
                }
                accs[nt][e] = s;
            }
            mx0 = fmaxf(mx0, fmaxf(accs[nt][0], accs[nt][1]));
            mx1 = fmaxf(mx1, fmaxf(accs[nt][2], accs[nt][3]));
        }
        mx0 = fmaxf(mx0, __shfl_xor_sync(0xffffffffu, mx0, 1));
        mx0 = fmaxf(mx0, __shfl_xor_sync(0xffffffffu, mx0, 2));
        mx1 = fmaxf(mx1, __shfl_xor_sync(0xffffffffu, mx1, 1));
        mx1 = fmaxf(mx1, __shfl_xor_sync(0xffffffffu, mx1, 2));
        const float mn0 = fmaxf(m0, mx0), mn1 = fmaxf(m1, mx1);
        const float al0 = __expf(m0 - mn0), al1 = __expf(m1 - mn1);
        float rs0 = 0.f, rs1 = 0.f;
#pragma unroll
        for (int nt = 0; nt < 8; nt++) {
            accs[nt][0] = __expf(accs[nt][0] - mn0);
            accs[nt][1] = __expf(accs[nt][1] - mn0);
            accs[nt][2] = __expf(accs[nt][2] - mn1);
            accs[nt][3] = __expf(accs[nt][3] - mn1);
            rs0 += accs[nt][0] + accs[nt][1];
            rs1 += accs[nt][2] + accs[nt][3];
        }
        rs0 += __shfl_xor_sync(0xffffffffu, rs0, 1);
        rs0 += __shfl_xor_sync(0xffffffffu, rs0, 2);
        rs1 += __shfl_xor_sync(0xffffffffu, rs1, 1);
        rs1 += __shfl_xor_sync(0xffffffffu, rs1, 2);
        l0 = l0 * al0 + rs0; l1 = l1 * al1 + rs1;
        m0 = mn0; m1 = mn1;
#pragma unroll
        for (int nt = 0; nt < 8; nt++) {
            acco[nt][0] *= al0; acco[nt][1] *= al0;
            acco[nt][2] *= al1; acco[nt][3] *= al1;
        }

        // ---- O += P V (hi/lo 3-mma), P from registers ----
#pragma unroll
        for (int c = 0; c < 4; c++) {
            uint32_t pah[4], pal[4];
            split2(accs[2 * c][0], accs[2 * c][1], pah[0], pal[0]);
            split2(accs[2 * c][2], accs[2 * c][3], pah[1], pal[1]);
            split2(accs[2 * c + 1][0], accs[2 * c + 1][1], pah[2], pal[2]);
            split2(accs[2 * c + 1][2], accs[2 * c + 1][3], pah[3], pal[3]);
            const uint32_t vb = ss + 2 * AKV_BYTES +
                (c * 16 + (bg & 1) * 8 + (lane & 7)) * 144 + (bg >> 1) * 16;
#pragma unroll
            for (int dp = 0; dp < 4; dp++) {
                uint32_t vh4[4], vl4[4];
                ldsm_x4_t(vb + dp * 32, vh4);
                ldsm_x4_t(vb + AKV_BYTES + dp * 32, vl4);
#pragma unroll
                for (int hf = 0; hf < 2; hf++) {
                    const int nt = dp * 2 + hf;
                    mma_bf16(acco[nt], pah, vh4[hf * 2], vh4[hf * 2 + 1]);
                    mma_bf16(acco[nt], pah, vl4[hf * 2], vl4[hf * 2 + 1]);
                    mma_bf16(acco[nt], pal, vh4[hf * 2], vh4[hf * 2 + 1]);
                }
            }
        }
        __syncthreads();
    }

    // ---- epilogue: normalize, write ctx bf16 hi/lo ----
    const int b = bh >> 4, h = bh & 15;
    const float i0 = 1.f / l0, i1 = 1.f / l1;
    const size_t tok = (size_t)b * SEQ + qb * 128 + wm * 16 + (lane >> 2);
#pragma unroll
    for (int nt = 0; nt < 8; nt++) {
        const int d0 = h * DHEAD + nt * 8 + (lane & 3) * 2;
        uint32_t hi, lo;
        split2(acco[nt][0] * i0, acco[nt][1] * i0, hi, lo);
        *reinterpret_cast<uint32_t*>(Ch + tok * DMODEL + d0) = hi;
        *reinterpret_cast<uint32_t*>(Cl + tok * DMODEL + d0) = lo;
        split2(acco[nt][2] * i1, acco[nt][3] * i1, hi, lo);
        *reinterpret_cast<uint32_t*>(Ch + (tok + 8) * DMODEL + d0) = hi;
        *reinterpret_cast<uint32_t*>(Cl + (tok + 8) * DMODEL + d0) = lo;
    }
}

// ---------------------------------------------------------------------------
extern "C" void kernel_launch(void* const* d_in, const int* in_sizes, int n_in,
                              void* d_out, int out_size)
{
    const float* q   = (const float*)d_in[0];
    const float* k   = (const float*)d_in[1];
    const float* v   = (const float*)d_in[2];
    const float* w_q = (const float*)d_in[4];
    const float* b_q = (const float*)d_in[5];
    const float* w_k = (const float*)d_in[6];
    const float* b_k = (const float*)d_in[7];
    const float* w_v = (const float*)d_in[8];
    const float* b_v = (const float*)d_in[9];
    const float* w_o = (const float*)d_in[10];
    const float* b_o = (const float*)d_in[11];
    float* out = (float*)d_out;

    __nv_bfloat16 *ah, *al, *wh, *wl, *ch, *cl;
    __nv_bfloat16 *qh, *ql, *kh, *kl, *vh, *vl;
    cudaGetSymbolAddress((void**)&ah, g_ah);
    cudaGetSymbolAddress((void**)&al, g_al);
    cudaGetSymbolAddress((void**)&wh, g_wh);
    cudaGetSymbolAddress((void**)&wl, g_wl);
    cudaGetSymbolAddress((void**)&ch, g_ch);
    cudaGetSymbolAddress((void**)&cl, g_cl);
    cudaGetSymbolAddress((void**)&qh, g_qh);
    cudaGetSymbolAddress((void**)&ql, g_ql);
    cudaGetSymbolAddress((void**)&kh, g_kh2);
    cudaGetSymbolAddress((void**)&kl, g_kl2);
    cudaGetSymbolAddress((void**)&vh, g_vh2);
    cudaGetSymbolAddress((void**)&vl, g_vl2);

    static bool attr_set = false;
    if (!attr_set) {
        cudaFuncSetAttribute(gemm_mma<0>,
                             cudaFuncAttributeMaxDynamicSharedMemorySize, GEMM_SMEM);
        cudaFuncSetAttribute(gemm_mma<1>,
                             cudaFuncAttributeMaxDynamicSharedMemorySize, GEMM_SMEM);
        cudaFuncSetAttribute(attn_mma,
                             cudaFuncAttributeMaxDynamicSharedMemorySize, ATT_SMEM);
        attr_set = true;
    }

    const int nX = GM * GK;
    const int nW = GN * GK;

    SplitArgs sa;
    sa.src[0] = q;   sa.hi[0] = ah;            sa.lo[0] = al;
    sa.src[1] = k;   sa.hi[1] = ah + (size_t)nX;     sa.lo[1] = al + (size_t)nX;
    sa.src[2] = v;   sa.hi[2] = ah + 2 * (size_t)nX; sa.lo[2] = al + 2 * (size_t)nX;
    sa.src[3] = w_q; sa.hi[3] = wh;            sa.lo[3] = wl;
    sa.src[4] = w_k; sa.hi[4] = wh + (size_t)nW;     sa.lo[4] = wl + (size_t)nW;
    sa.src[5] = w_v; sa.hi[5] = wh + 2 * (size_t)nW; sa.lo[5] = wl + 2 * (size_t)nW;
    sa.src[6] = w_o; sa.hi[6] = wh + 3 * (size_t)nW; sa.lo[6] = wl + 3 * (size_t)nW;
    split_all_kernel<<<3 * 4096 + 4 * 1024, 256>>>(sa);

    const dim3 gG(GN / 128, GM / 128);   // (8, 32)
    gemm_mma<1><<<gG, 256, GEMM_SMEM>>>(ah, al, wh, wl, b_q, nullptr, qh, ql);
    gemm_mma<1><<<gG, 256, GEMM_SMEM>>>(ah + (size_t)nX, al + (size_t)nX,
                                        wh + (size_t)nW, wl + (size_t)nW, b_k, nullptr, kh, kl);
    gemm_mma<1><<<gG, 256, GEMM_SMEM>>>(ah + 2 * (size_t)nX, al + 2 * (size_t)nX,
                                        wh + 2 * (size_t)nW, wl + 2 * (size_t)nW, b_v, nullptr, vh, vl);

    attn_mma<<<dim3(SEQ / 128, BSZ * NHEAD), 256, ATT_SMEM>>>(
        qh, ql, kh, kl, vh, vl, ch, cl);

    gemm_mma<0><<<gG, 256, GEMM_SMEM>>>(ch, cl,
                                        wh + 3 * (size_t)nW, wl + 3 * (size_t)nW, b_o, out,
                                        nullptr, nullptr);
}

// round 12
// speedup vs baseline: 2.6748x; 1.0096x over previous
#include <cuda_runtime.h>
#include <cuda_bf16.h>
#include <cstdint>

#define BSZ 2
#define SEQ 2048
#define DMODEL 1024
#define NHEAD 16
#define DHEAD 64

constexpr int GM = BSZ * SEQ;     // 4096
constexpr int GN = DMODEL;        // 1024
constexpr int GK = DMODEL;        // 1024

// ---------------- scratch (allocation-free device globals) ----------------
__device__ __nv_bfloat16 g_ah[3][GM * GK];   // q,k,v inputs hi (GEMM A)
__device__ __nv_bfloat16 g_al[3][GM * GK];   // lo
__device__ __nv_bfloat16 g_wh[4][GN * GK];   // w_q,w_k,w_v,w_o hi
__device__ __nv_bfloat16 g_wl[4][GN * GK];   // lo
// head-layout projected tensors [B,H,S,DK], hi/lo
__device__ __nv_bfloat16 g_qh[BSZ * NHEAD * SEQ * DHEAD];
__device__ __nv_bfloat16 g_ql[BSZ * NHEAD * SEQ * DHEAD];
__device__ __nv_bfloat16 g_kh2[BSZ * NHEAD * SEQ * DHEAD];
__device__ __nv_bfloat16 g_kl2[BSZ * NHEAD * SEQ * DHEAD];
__device__ __nv_bfloat16 g_vh2[BSZ * NHEAD * SEQ * DHEAD];
__device__ __nv_bfloat16 g_vl2[BSZ * NHEAD * SEQ * DHEAD];
// attention context [B*S, DMODEL] hi/lo (o-proj A operand)
__device__ __nv_bfloat16 g_ch[GM * GK];
__device__ __nv_bfloat16 g_cl[GM * GK];

// ---------------------------- PTX helpers ---------------------------------
__device__ __forceinline__ uint32_t smem_u32(const void* p) {
    uint32_t a;
    asm("{ .reg .u64 t; cvta.to.shared.u64 t, %1; cvt.u32.u64 %0, t; }"
        : "=r"(a) : "l"(p));
    return a;
}
__device__ __forceinline__ void cp16(uint32_t dst, const void* src) {
    asm volatile("cp.async.cg.shared.global [%0], [%1], 16;"
                 :: "r"(dst), "l"(src) : "memory");
}
#define CP_COMMIT() asm volatile("cp.async.commit_group;" ::: "memory")
#define CP_WAIT1()  asm volatile("cp.async.wait_group 1;" ::: "memory")

__device__ __forceinline__ void ldsm_x4(uint32_t addr, uint32_t* r) {
    asm volatile("ldmatrix.sync.aligned.m8n8.x4.shared.b16 {%0,%1,%2,%3}, [%4];"
                 : "=r"(r[0]), "=r"(r[1]), "=r"(r[2]), "=r"(r[3]) : "r"(addr));
}
__device__ __forceinline__ void ldsm_x4_t(uint32_t addr, uint32_t* r) {
    asm volatile("ldmatrix.sync.aligned.m8n8.x4.trans.shared.b16 {%0,%1,%2,%3}, [%4];"
                 : "=r"(r[0]), "=r"(r[1]), "=r"(r[2]), "=r"(r[3]) : "r"(addr));
}
__device__ __forceinline__ void mma_bf16(float* d, const uint32_t* a,
                                         uint32_t b0, uint32_t b1) {
    asm volatile("mma.sync.aligned.m16n8k16.row.col.f32.bf16.bf16.f32 "
                 "{%0,%1,%2,%3}, {%4,%5,%6,%7}, {%8,%9}, {%0,%1,%2,%3};"
                 : "+f"(d[0]), "+f"(d[1]), "+f"(d[2]), "+f"(d[3])
                 : "r"(a[0]), "r"(a[1]), "r"(a[2]), "r"(a[3]),
                   "r"(b0), "r"(b1));
}
// split two floats into packed bf16x2 hi and lo words
__device__ __forceinline__ void split2(float a, float b, uint32_t& hi, uint32_t& lo) {
    __nv_bfloat16 ha = __float2bfloat16(a), hb = __float2bfloat16(b);
    __nv_bfloat16 la = __float2bfloat16(a - __bfloat162float(ha));
    __nv_bfloat16 lb = __float2bfloat16(b - __bfloat162float(hb));
    hi = ((uint32_t)__bfloat16_as_ushort(hb) << 16) | __bfloat16_as_ushort(ha);
    lo = ((uint32_t)__bfloat16_as_ushort(lb) << 16) | __bfloat16_as_ushort(la);
}

// ---------------------------------------------------------------------------
// fused fp32 -> (hi, lo) bf16 split for all 7 tensors in one launch
// ---------------------------------------------------------------------------
struct SplitArgs {
    const float* src[7];
    __nv_bfloat16* hi[7];
    __nv_bfloat16* lo[7];
};

__global__ void __launch_bounds__(256) split_all_kernel(SplitArgs args)
{
    int b = blockIdx.x;
    int seg, off;
    if (b < 3 * 4096) { seg = b >> 12; off = b & 4095; }
    else { b -= 3 * 4096; seg = 3 + (b >> 10); off = b & 1023; }
    const int i = (off * 256 + threadIdx.x) * 4;
    float4 v = *reinterpret_cast<const float4*>(args.src[seg] + i);
    uint32_t h01, h23, l01, l23;
    split2(v.x, v.y, h01, l01);
    split2(v.z, v.w, h23, l23);
    *reinterpret_cast<uint2*>(args.hi[seg] + i) = make_uint2(h01, h23);
    *reinterpret_cast<uint2*>(args.lo[seg] + i) = make_uint2(l01, l23);
}

// ---------------------------------------------------------------------------
// mma.sync bf16 GEMM:  C = A @ W^T + bias, hi/lo split (3 HMMAs / product).
// Batched over blockIdx.z (QKV in one launch). Term-major inner loop.
// MODE 0: fp32 output row-major.  MODE 1: bf16 hi/lo head layout.
// ---------------------------------------------------------------------------
constexpr int TILE_B = 128 * 80;
constexpr int STAGE  = 4 * TILE_B;
constexpr int GEMM_SMEM = 2 * STAGE; // 81920
constexpr int NC = GK / 32;

struct GemmBatch {
    const __nv_bfloat16* Ah[3];
    const __nv_bfloat16* Al[3];
    const __nv_bfloat16* Wh[3];
    const __nv_bfloat16* Wl[3];
    const float* bias[3];
    float* C[3];
    __nv_bfloat16* Ch[3];
    __nv_bfloat16* Cl[3];
};

template <int MODE>
__global__ void __launch_bounds__(256, 2) gemm_mma(GemmBatch args)
{
    extern __shared__ __align__(128) uint8_t smem[];
    const uint32_t sbase = smem_u32(smem);
    const int z = blockIdx.z;
    const int tid = threadIdx.x;
    const int lane = tid & 31;
    const int wid = tid >> 5;
    const int warp_m = wid >> 1;
    const int warp_n = wid & 1;
    const int m0 = blockIdx.y * 128;
    const int n0 = blockIdx.x * 128;

    const int lrow = tid >> 1;
    const int lq = tid & 1;
    const __nv_bfloat16* srcs[4] = {
        args.Ah[z] + (size_t)(m0 + lrow) * GK + lq * 16,
        args.Al[z] + (size_t)(m0 + lrow) * GK + lq * 16,
        args.Wh[z] + (size_t)(n0 + lrow) * GK + lq * 16,
        args.Wl[z] + (size_t)(n0 + lrow) * GK + lq * 16};
    const uint32_t sdst = sbase + lrow * 80 + lq * 32;

    float acc[2][8][4];
#pragma unroll
    for (int mt = 0; mt < 2; mt++)
#pragma unroll
        for (int nt = 0; nt < 8; nt++)
#pragma unroll
            for (int r = 0; r < 4; r++) acc[mt][nt][r] = 0.f;

    {
#pragma unroll
        for (int t = 0; t < 4; t++) {
            cp16(sdst + t * TILE_B, srcs[t]);
            cp16(sdst + t * TILE_B + 16, srcs[t] + 8);
        }
        CP_COMMIT();
    }

    for (int c = 0; c < NC; c++) {
        if (c + 1 < NC) {
            const uint32_t st = ((c + 1) & 1) * STAGE;
#pragma unroll
            for (int t = 0; t < 4; t++) {
                cp16(sdst + st + t * TILE_B, srcs[t] + (c + 1) * 32);
                cp16(sdst + st + t * TILE_B + 16, srcs[t] + (c + 1) * 32 + 8);
            }
        }
        CP_COMMIT();
        CP_WAIT1();
        __syncthreads();

        const uint32_t st = sbase + (c & 1) * STAGE;
#pragma unroll
        for (int k16 = 0; k16 < 2; k16++) {
            uint32_t ah[2][4], al[2][4];
            const uint32_t a_base =
                st + (warp_m * 32 + (lane & 15)) * 80 + ((lane >> 4) * 16) + k16 * 32;
#pragma unroll
            for (int mt = 0; mt < 2; mt++) {
                ldsm_x4(a_base + mt * 16 * 80, ah[mt]);
                ldsm_x4(a_base + TILE_B + mt * 16 * 80, al[mt]);
            }
            const int bg = lane >> 3;
            const uint32_t b_base =
                st + 2 * TILE_B +
                (warp_n * 64 + (bg >> 1) * 8 + (lane & 7)) * 80 +
                ((bg & 1) * 16) + k16 * 32;
#pragma unroll
            for (int ntp = 0; ntp < 4; ntp++) {
                uint32_t bh[4], bl[4];
                ldsm_x4(b_base + ntp * 16 * 80, bh);
                ldsm_x4(b_base + TILE_B + ntp * 16 * 80, bl);
                // term-major: same-acc reuse distance 4 instead of 1
#pragma unroll
                for (int mt = 0; mt < 2; mt++)
#pragma unroll
                    for (int hf = 0; hf < 2; hf++)
                        mma_bf16(acc[mt][ntp * 2 + hf], ah[mt],
                                 bh[hf * 2], bh[hf * 2 + 1]);
#pragma unroll
                for (int mt = 0; mt < 2; mt++)
#pragma unroll
                    for (int hf = 0; hf < 2; hf++)
                        mma_bf16(acc[mt][ntp * 2 + hf], ah[mt],
                                 bl[hf * 2], bl[hf * 2 + 1]);
#pragma unroll
                for (int mt = 0; mt < 2; mt++)
#pragma unroll
                    for (int hf = 0; hf < 2; hf++)
                        mma_bf16(acc[mt][ntp * 2 + hf], al[mt],
                                 bh[hf * 2], bh[hf * 2 + 1]);
            }
        }
        __syncthreads();
    }

#pragma unroll
    for (int mt = 0; mt < 2; mt++) {
#pragma unroll
        for (int nt = 0; nt < 8; nt++) {
            const int colg = n0 + warp_n * 64 + nt * 8 + (lane & 3) * 2;
            const float2 bv = *reinterpret_cast<const float2*>(&args.bias[z][colg]);
#pragma unroll
            for (int half = 0; half < 2; half++) {
                const int rowg = m0 + warp_m * 32 + mt * 16 + (lane >> 2) + half * 8;
                const float ox = acc[mt][nt][half * 2 + 0] + bv.x;
                const float oy = acc[mt][nt][half * 2 + 1] + bv.y;
                if (MODE == 1) {
                    const int b = rowg >> 11, s = rowg & 2047;
                    const int h = colg >> 6, d = colg & 63;
                    const size_t idx = (((size_t)b * NHEAD + h) * SEQ + s) * DHEAD + d;
                    uint32_t hi, lo;
                    split2(ox, oy, hi, lo);
                    *reinterpret_cast<uint32_t*>(args.Ch[z] + idx) = hi;
                    *reinterpret_cast<uint32_t*>(args.Cl[z] + idx) = lo;
                } else {
                    float2 o; o.x = ox; o.y = oy;
                    *reinterpret_cast<float2*>(&args.C[z][(size_t)rowg * GN + colg]) = o;
                }
            }
        }
    }
}

// ---------------------------------------------------------------------------
// Tensor-core flash attention (causal), bf16 hi/lo mma.sync, term-major.
// ---------------------------------------------------------------------------
constexpr int AQ_BYTES  = 128 * 144;
constexpr int AKV_BYTES = 64 * 144;
constexpr int ASTAGE    = 4 * AKV_BYTES;
constexpr int ATT_SMEM  = 2 * AQ_BYTES + 2 * ASTAGE;  // 110592

__global__ void __launch_bounds__(256, 2) attn_mma(
    const __nv_bfloat16* __restrict__ Qh, const __nv_bfloat16* __restrict__ Ql,
    const __nv_bfloat16* __restrict__ Kh, const __nv_bfloat16* __restrict__ Kl,
    const __nv_bfloat16* __restrict__ Vh, const __nv_bfloat16* __restrict__ Vl,
    __nv_bfloat16* __restrict__ Ch, __nv_bfloat16* __restrict__ Cl)
{
    extern __shared__ __align__(128) uint8_t smem[];
    const uint32_t sbase = smem_u32(smem);
    const int tid = threadIdx.x, lane = tid & 31, wm = tid >> 5;
    const int qb = gridDim.x - 1 - blockIdx.x;   // heavy tiles first
    const int bh = blockIdx.y;
    const size_t base = (size_t)bh * SEQ * DHEAD;
    const int nkb = 2 * qb + 2;

    {
        const int r = tid >> 1, half = tid & 1;
        const size_t g = base + (size_t)(qb * 128 + r) * DHEAD + half * 32;
        const uint32_t d = sbase + r * 144 + half * 64;
#pragma unroll
        for (int i = 0; i < 4; i++) {
            cp16(d + i * 16, Qh + g + i * 8);
            cp16(d + AQ_BYTES + i * 16, Ql + g + i * 8);
        }
    }
    auto loadKV = [&](int kb) {
        const uint32_t ss = sbase + 2 * AQ_BYTES + (kb & 1) * ASTAGE;
        const int r = tid >> 2, seg = tid & 3;
        const size_t g = base + (size_t)(kb * 64 + r) * DHEAD + seg * 16;
        const uint32_t d = ss + r * 144 + seg * 32;
        cp16(d, Kh + g);                      cp16(d + 16, Kh + g + 8);
        cp16(d + AKV_BYTES, Kl + g);          cp16(d + AKV_BYTES + 16, Kl + g + 8);
        cp16(d + 2 * AKV_BYTES, Vh + g);      cp16(d + 2 * AKV_BYTES + 16, Vh + g + 8);
        cp16(d + 3 * AKV_BYTES, Vl + g);      cp16(d + 3 * AKV_BYTES + 16, Vl + g + 8);
    };
    loadKV(0);
    CP_COMMIT();

    float m0 = -1e30f, m1 = -1e30f, l0 = 0.f, l1 = 0.f;
    float acco[8][4];
#pragma unroll
    for (int nt = 0; nt < 8; nt++)
#pragma unroll
        for (int e = 0; e < 4; e++) acco[nt][e] = 0.f;

    const int bg = lane >> 3;
    const uint32_t aq = sbase + (wm * 16 + (lane & 15)) * 144 + (lane >> 4) * 16;

    for (int kb = 0; kb < nkb; kb++) {
        if (kb + 1 < nkb) loadKV(kb + 1);
        CP_COMMIT();
        CP_WAIT1();
        __syncthreads();
        const uint32_t ss = sbase + 2 * AQ_BYTES + (kb & 1) * ASTAGE;

        // ---- S = Q K^T (hi/lo 3-mma, term-major) ----
        float accs[8][4];
#pragma unroll
        for (int nt = 0; nt < 8; nt++)
#pragma unroll
            for (int e = 0; e < 4; e++) accs[nt][e] = 0.f;

        const uint32_t kbase = ss + ((bg >> 1) * 8 + (lane & 7)) * 144 + (bg & 1) * 16;
#pragma unroll
        for (int kc = 0; kc < 4; kc++) {
            uint32_t qh4[4], ql4[4];
            ldsm_x4(aq + kc * 32, qh4);
            ldsm_x4(aq + AQ_BYTES + kc * 32, ql4);
#pragma unroll
            for (int ntp = 0; ntp < 4; ntp++) {
                uint32_t kh4[4], kl4[4];
                ldsm_x4(kbase + ntp * 16 * 144 + kc * 32, kh4);
                ldsm_x4(kbase + AKV_BYTES + ntp * 16 * 144 + kc * 32, kl4);
#pragma unroll
                for (int hf = 0; hf < 2; hf++)
                    mma_bf16(accs[ntp * 2 + hf], qh4, kh4[hf * 2], kh4[hf * 2 + 1]);
#pragma unroll
                for (int hf = 0; hf < 2; hf++)
                    mma_bf16(accs[ntp * 2 + hf], qh4, kl4[hf * 2], kl4[hf * 2 + 1]);
#pragma unroll
                for (int hf = 0; hf < 2; hf++)
                    mma_bf16(accs[ntp * 2 + hf], ql4, kh4[hf * 2], kh4[hf * 2 + 1]);
            }
        }

        // ---- online softmax ----
        const int r0 = qb * 128 + wm * 16 + (lane >> 2);
        const bool needMask = (kb * 64 + 63 > qb * 128 + wm * 16);
        float mx0 = -1e30f, mx1 = -1e30f;
#pragma unroll
        for (int nt = 0; nt < 8; nt++) {
#pragma unroll
            for (int e = 0; e < 4; e++) {
                float s = accs[nt][e] * 0.125f;
                if (needMask) {
                    const int col = kb * 64 + nt * 8 + (lane & 3) * 2 + (e & 1);
                    const int row = r0 + (e >> 1) * 8;
                    if (col > row) s = -1e30f;
                }
                accs[nt][e] = s;
            }
            mx0 = fmaxf(mx0, fmaxf(accs[nt][0], accs[nt][1]));
            mx1 = fmaxf(mx1, fmaxf(accs[nt][2], accs[nt][3]));
        }
        mx0 = fmaxf(mx0, __shfl_xor_sync(0xffffffffu, mx0, 1));
        mx0 = fmaxf(mx0, __shfl_xor_sync(0xffffffffu, mx0, 2));
        mx1 = fmaxf(mx1, __shfl_xor_sync(0xffffffffu, mx1, 1));
        mx1 = fmaxf(mx1, __shfl_xor_sync(0xffffffffu, mx1, 2));
        const float mn0 = fmaxf(m0, mx0), mn1 = fmaxf(m1, mx1);
        const float al0 = __expf(m0 - mn0), al1 = __expf(m1 - mn1);
        float rs0 = 0.f, rs1 = 0.f;
#pragma unroll
        for (int nt = 0; nt < 8; nt++) {
            accs[nt][0] = __expf(accs[nt][0] - mn0);
            accs[nt][1] = __expf(accs[nt][1] - mn0);
            accs[nt][2] = __expf(accs[nt][2] - mn1);
            accs[nt][3] = __expf(accs[nt][3] - mn1);
            rs0 += accs[nt][0] + accs[nt][1];
            rs1 += accs[nt][2] + accs[nt][3];
        }
        rs0 += __shfl_xor_sync(0xffffffffu, rs0, 1);
        rs0 += __shfl_xor_sync(0xffffffffu, rs0, 2);
        rs1 += __shfl_xor_sync(0xffffffffu, rs1, 1);
        rs1 += __shfl_xor_sync(0xffffffffu, rs1, 2);
        l0 = l0 * al0 + rs0; l1 = l1 * al1 + rs1;
        m0 = mn0; m1 = mn1;
#pragma unroll
        for (int nt = 0; nt < 8; nt++) {
            acco[nt][0] *= al0; acco[nt][1] *= al0;
            acco[nt][2] *= al1; acco[nt][3] *= al1;
        }

        // ---- O += P V (hi/lo 3-mma, term-major) ----
#pragma unroll
        for (int c = 0; c < 4; c++) {
            uint32_t pah[4], pal[4];
            split2(accs[2 * c][0], accs[2 * c][1], pah[0], pal[0]);
            split2(accs[2 * c][2], accs[2 * c][3], pah[1], pal[1]);
            split2(accs[2 * c + 1][0], accs[2 * c + 1][1], pah[2], pal[2]);
            split2(accs[2 * c + 1][2], accs[2 * c + 1][3], pah[3], pal[3]);
            const uint32_t vb = ss + 2 * AKV_BYTES +
                (c * 16 + (bg & 1) * 8 + (lane & 7)) * 144 + (bg >> 1) * 16;
#pragma unroll
            for (int dp = 0; dp < 4; dp++) {
                uint32_t vh4[4], vl4[4];
                ldsm_x4_t(vb + dp * 32, vh4);
                ldsm_x4_t(vb + AKV_BYTES + dp * 32, vl4);
#pragma unroll
                for (int hf = 0; hf < 2; hf++)
                    mma_bf16(acco[dp * 2 + hf], pah, vh4[hf * 2], vh4[hf * 2 + 1]);
#pragma unroll
                for (int hf = 0; hf < 2; hf++)
                    mma_bf16(acco[dp * 2 + hf], pah, vl4[hf * 2], vl4[hf * 2 + 1]);
#pragma unroll
                for (int hf = 0; hf < 2; hf++)
                    mma_bf16(acco[dp * 2 + hf], pal, vh4[hf * 2], vh4[hf * 2 + 1]);
            }
        }
        __syncthreads();
    }

    // ---- epilogue: normalize, write ctx bf16 hi/lo ----
    const int b = bh >> 4, h = bh & 15;
    const float i0 = 1.f / l0, i1 = 1.f / l1;
    const size_t tok = (size_t)b * SEQ + qb * 128 + wm * 16 + (lane >> 2);
#pragma unroll
    for (int nt = 0; nt < 8; nt++) {
        const int d0 = h * DHEAD + nt * 8 + (lane & 3) * 2;
        uint32_t hi, lo;
        split2(acco[nt][0] * i0, acco[nt][1] * i0, hi, lo);
        *reinterpret_cast<uint32_t*>(Ch + tok * DMODEL + d0) = hi;
        *reinterpret_cast<uint32_t*>(Cl + tok * DMODEL + d0) = lo;
        split2(acco[nt][2] * i1, acco[nt][3] * i1, hi, lo);
        *reinterpret_cast<uint32_t*>(Ch + (tok + 8) * DMODEL + d0) = hi;
        *reinterpret_cast<uint32_t*>(Cl + (tok + 8) * DMODEL + d0) = lo;
    }
}

// ---------------------------------------------------------------------------
extern "C" void kernel_launch(void* const* d_in, const int* in_sizes, int n_in,
                              void* d_out, int out_size)
{
    const float* q   = (const float*)d_in[0];
    const float* k   = (const float*)d_in[1];
    const float* v   = (const float*)d_in[2];
    const float* w_q = (const float*)d_in[4];
    const float* b_q = (const float*)d_in[5];
    const float* w_k = (const float*)d_in[6];
    const float* b_k = (const float*)d_in[7];
    const float* w_v = (const float*)d_in[8];
    const float* b_v = (const float*)d_in[9];
    const float* w_o = (const float*)d_in[10];
    const float* b_o = (const float*)d_in[11];
    float* out = (float*)d_out;

    __nv_bfloat16 *ah, *al, *wh, *wl, *ch, *cl;
    __nv_bfloat16 *qh, *ql, *kh, *kl, *vh, *vl;
    cudaGetSymbolAddress((void**)&ah, g_ah);
    cudaGetSymbolAddress((void**)&al, g_al);
    cudaGetSymbolAddress((void**)&wh, g_wh);
    cudaGetSymbolAddress((void**)&wl, g_wl);
    cudaGetSymbolAddress((void**)&ch, g_ch);
    cudaGetSymbolAddress((void**)&cl, g_cl);
    cudaGetSymbolAddress((void**)&qh, g_qh);
    cudaGetSymbolAddress((void**)&ql, g_ql);
    cudaGetSymbolAddress((void**)&kh, g_kh2);
    cudaGetSymbolAddress((void**)&kl, g_kl2);
    cudaGetSymbolAddress((void**)&vh, g_vh2);
    cudaGetSymbolAddress((void**)&vl, g_vl2);

    static bool attr_set = false;
    if (!attr_set) {
        cudaFuncSetAttribute(gemm_mma<0>,
                             cudaFuncAttributeMaxDynamicSharedMemorySize, GEMM_SMEM);
        cudaFuncSetAttribute(gemm_mma<1>,
                             cudaFuncAttributeMaxDynamicSharedMemorySize, GEMM_SMEM);
        cudaFuncSetAttribute(attn_mma,
                             cudaFuncAttributeMaxDynamicSharedMemorySize, ATT_SMEM);
        attr_set = true;
    }

    const int nX = GM * GK;
    const int nW = GN * GK;

    SplitArgs sa;
    sa.src[0] = q;   sa.hi[0] = ah;                  sa.lo[0] = al;
    sa.src[1] = k;   sa.hi[1] = ah + (size_t)nX;     sa.lo[1] = al + (size_t)nX;
    sa.src[2] = v;   sa.hi[2] = ah + 2 * (size_t)nX; sa.lo[2] = al + 2 * (size_t)nX;
    sa.src[3] = w_q; sa.hi[3] = wh;                  sa.lo[3] = wl;
    sa.src[4] = w_k; sa.hi[4] = wh + (size_t)nW;     sa.lo[4] = wl + (size_t)nW;
    sa.src[5] = w_v; sa.hi[5] = wh + 2 * (size_t)nW; sa.lo[5] = wl + 2 * (size_t)nW;
    sa.src[6] = w_o; sa.hi[6] = wh + 3 * (size_t)nW; sa.lo[6] = wl + 3 * (size_t)nW;
    split_all_kernel<<<3 * 4096 + 4 * 1024, 256>>>(sa);

    // merged QKV projection: one launch, grid.z selects tensor
    GemmBatch gb;
    gb.Ah[0] = ah;                  gb.Al[0] = al;
    gb.Ah[1] = ah + (size_t)nX;     gb.Al[1] = al + (size_t)nX;
    gb.Ah[2] = ah + 2 * (size_t)nX; gb.Al[2] = al + 2 * (size_t)nX;
    gb.Wh[0] = wh;                  gb.Wl[0] = wl;
    gb.Wh[1] = wh + (size_t)nW;     gb.Wl[1] = wl + (size_t)nW;
    gb.Wh[2] = wh + 2 * (size_t)nW; gb.Wl[2] = wl + 2 * (size_t)nW;
    gb.bias[0] = b_q; gb.bias[1] = b_k; gb.bias[2] = b_v;
    gb.C[0] = gb.C[1] = gb.C[2] = nullptr;
    gb.Ch[0] = qh; gb.Cl[0] = ql;
    gb.Ch[1] = kh; gb.Cl[1] = kl;
    gb.Ch[2] = vh; gb.Cl[2] = vl;
    gemm_mma<1><<<dim3(GN / 128, GM / 128, 3), 256, GEMM_SMEM>>>(gb);

    attn_mma<<<dim3(SEQ / 128, BSZ * NHEAD), 256, ATT_SMEM>>>(
        qh, ql, kh, kl, vh, vl, ch, cl);

    GemmBatch go;
    go.Ah[0] = ch; go.Al[0] = cl;
    go.Wh[0] = wh + 3 * (size_t)nW; go.Wl[0] = wl + 3 * (size_t)nW;
    go.bias[0] = b_o;
    go.C[0] = out;
    go.Ch[0] = nullptr; go.Cl[0] = nullptr;
    go.Ah[1] = go.Ah[2] = nullptr; go.Al[1] = go.Al[2] = nullptr;
    go.Wh[1] = go.Wh[2] = nullptr; go.Wl[1] = go.Wl[2] = nullptr;
    go.bias[1] = go.bias[2] = nullptr;
    go.C[1] = go.C[2] = nullptr;
    go.Ch[1] = go.Ch[2] = nullptr; go.Cl[1] = go.Cl[2] = nullptr;
    gemm_mma<0><<<dim3(GN / 128, GM / 128, 1), 256, GEMM_SMEM>>>(go);
}

// round 13
// speedup vs baseline: 2.6975x; 1.0085x over previous
#include <cuda_runtime.h>
#include <cuda_bf16.h>
#include <cstdint>

#define BSZ 2
#define SEQ 2048
#define DMODEL 1024
#define NHEAD 16
#define DHEAD 64

constexpr int GM = BSZ * SEQ;     // 4096
constexpr int GN = DMODEL;        // 1024
constexpr int GK = DMODEL;        // 1024

// ---------------- scratch (allocation-free device globals) ----------------
__device__ __nv_bfloat16 g_ah[3][GM * GK];
__device__ __nv_bfloat16 g_al[3][GM * GK];
__device__ __nv_bfloat16 g_wh[4][GN * GK];
__device__ __nv_bfloat16 g_wl[4][GN * GK];
__device__ __nv_bfloat16 g_qh[BSZ * NHEAD * SEQ * DHEAD];
__device__ __nv_bfloat16 g_ql[BSZ * NHEAD * SEQ * DHEAD];
__device__ __nv_bfloat16 g_kh2[BSZ * NHEAD * SEQ * DHEAD];
__device__ __nv_bfloat16 g_kl2[BSZ * NHEAD * SEQ * DHEAD];
__device__ __nv_bfloat16 g_vh2[BSZ * NHEAD * SEQ * DHEAD];
__device__ __nv_bfloat16 g_vl2[BSZ * NHEAD * SEQ * DHEAD];
__device__ __nv_bfloat16 g_ch[GM * GK];
__device__ __nv_bfloat16 g_cl[GM * GK];

// ---------------------------- PTX helpers ---------------------------------
__device__ __forceinline__ uint32_t smem_u32(const void* p) {
    uint32_t a;
    asm("{ .reg .u64 t; cvta.to.shared.u64 t, %1; cvt.u32.u64 %0, t; }"
        : "=r"(a) : "l"(p));
    return a;
}
__device__ __forceinline__ void cp16(uint32_t dst, const void* src) {
    asm volatile("cp.async.cg.shared.global [%0], [%1], 16;"
                 :: "r"(dst), "l"(src) : "memory");
}
#define CP_COMMIT() asm volatile("cp.async.commit_group;" ::: "memory")
#define CP_WAIT1()  asm volatile("cp.async.wait_group 1;" ::: "memory")

__device__ __forceinline__ void ldsm_x4(uint32_t addr, uint32_t* r) {
    asm volatile("ldmatrix.sync.aligned.m8n8.x4.shared.b16 {%0,%1,%2,%3}, [%4];"
                 : "=r"(r[0]), "=r"(r[1]), "=r"(r[2]), "=r"(r[3]) : "r"(addr));
}
__device__ __forceinline__ void ldsm_x4_t(uint32_t addr, uint32_t* r) {
    asm volatile("ldmatrix.sync.aligned.m8n8.x4.trans.shared.b16 {%0,%1,%2,%3}, [%4];"
                 : "=r"(r[0]), "=r"(r[1]), "=r"(r[2]), "=r"(r[3]) : "r"(addr));
}
__device__ __forceinline__ void mma_bf16(float* d, const uint32_t* a,
                                         uint32_t b0, uint32_t b1) {
    asm volatile("mma.sync.aligned.m16n8k16.row.col.f32.bf16.bf16.f32 "
                 "{%0,%1,%2,%3}, {%4,%5,%6,%7}, {%8,%9}, {%0,%1,%2,%3};"
                 : "+f"(d[0]), "+f"(d[1]), "+f"(d[2]), "+f"(d[3])
                 : "r"(a[0]), "r"(a[1]), "r"(a[2]), "r"(a[3]),
                   "r"(b0), "r"(b1));
}
__device__ __forceinline__ void split2(float a, float b, uint32_t& hi, uint32_t& lo) {
    __nv_bfloat16 ha = __float2bfloat16(a), hb = __float2bfloat16(b);
    __nv_bfloat16 la = __float2bfloat16(a - __bfloat162float(ha));
    __nv_bfloat16 lb = __float2bfloat16(b - __bfloat162float(hb));
    hi = ((uint32_t)__bfloat16_as_ushort(hb) << 16) | __bfloat16_as_ushort(ha);
    lo = ((uint32_t)__bfloat16_as_ushort(lb) << 16) | __bfloat16_as_ushort(la);
}

// ---------------------------------------------------------------------------
// fused fp32 -> (hi, lo) bf16 split for all 7 tensors in one launch
// ---------------------------------------------------------------------------
struct SplitArgs {
    const float* src[7];
    __nv_bfloat16* hi[7];
    __nv_bfloat16* lo[7];
};

__global__ void __launch_bounds__(256) split_all_kernel(SplitArgs args)
{
    int b = blockIdx.x;
    int seg, off;
    if (b < 3 * 4096) { seg = b >> 12; off = b & 4095; }
    else { b -= 3 * 4096; seg = 3 + (b >> 10); off = b & 1023; }
    const int i = (off * 256 + threadIdx.x) * 4;
    float4 v = *reinterpret_cast<const float4*>(args.src[seg] + i);
    uint32_t h01, h23, l01, l23;
    split2(v.x, v.y, h01, l01);
    split2(v.z, v.w, h23, l23);
    *reinterpret_cast<uint2*>(args.hi[seg] + i) = make_uint2(h01, h23);
    *reinterpret_cast<uint2*>(args.lo[seg] + i) = make_uint2(l01, l23);
}

// ---------------------------------------------------------------------------
// mma.sync bf16 GEMM, hi/lo split. Fragments front-loaded per k16;
// 48 MMAs at same-acc reuse distance 16.
// ---------------------------------------------------------------------------
constexpr int TILE_B = 128 * 80;
constexpr int STAGE  = 4 * TILE_B;
constexpr int GEMM_SMEM = 2 * STAGE; // 81920
constexpr int NC = GK / 32;

struct GemmBatch {
    const __nv_bfloat16* Ah[3];
    const __nv_bfloat16* Al[3];
    const __nv_bfloat16* Wh[3];
    const __nv_bfloat16* Wl[3];
    const float* bias[3];
    float* C[3];
    __nv_bfloat16* Ch[3];
    __nv_bfloat16* Cl[3];
};

template <int MODE>
__global__ void __launch_bounds__(256, 2) gemm_mma(GemmBatch args)
{
    extern __shared__ __align__(128) uint8_t smem[];
    const uint32_t sbase = smem_u32(smem);
    const int z = blockIdx.z;
    const int tid = threadIdx.x;
    const int lane = tid & 31;
    const int wid = tid >> 5;
    const int warp_m = wid >> 1;
    const int warp_n = wid & 1;
    const int m0 = blockIdx.y * 128;
    const int n0 = blockIdx.x * 128;

    const int lrow = tid >> 1;
    const int lq = tid & 1;
    const __nv_bfloat16* srcs[4] = {
        args.Ah[z] + (size_t)(m0 + lrow) * GK + lq * 16,
        args.Al[z] + (size_t)(m0 + lrow) * GK + lq * 16,
        args.Wh[z] + (size_t)(n0 + lrow) * GK + lq * 16,
        args.Wl[z] + (size_t)(n0 + lrow) * GK + lq * 16};
    const uint32_t sdst = sbase + lrow * 80 + lq * 32;

    float acc[2][8][4];
#pragma unroll
    for (int mt = 0; mt < 2; mt++)
#pragma unroll
        for (int nt = 0; nt < 8; nt++)
#pragma unroll
            for (int r = 0; r < 4; r++) acc[mt][nt][r] = 0.f;

    {
#pragma unroll
        for (int t = 0; t < 4; t++) {
            cp16(sdst + t * TILE_B, srcs[t]);
            cp16(sdst + t * TILE_B + 16, srcs[t] + 8);
        }
        CP_COMMIT();
    }

    for (int c = 0; c < NC; c++) {
        if (c + 1 < NC) {
            const uint32_t st = ((c + 1) & 1) * STAGE;
#pragma unroll
            for (int t = 0; t < 4; t++) {
                cp16(sdst + st + t * TILE_B, srcs[t] + (c + 1) * 32);
                cp16(sdst + st + t * TILE_B + 16, srcs[t] + (c + 1) * 32 + 8);
            }
        }
        CP_COMMIT();
        CP_WAIT1();
        __syncthreads();

        const uint32_t st = sbase + (c & 1) * STAGE;
#pragma unroll
        for (int k16 = 0; k16 < 2; k16++) {
            // ---- front-load ALL fragments for this k16 ----
            uint32_t ah[2][4], al[2][4], bh[4][4], bl[4][4];
            const uint32_t a_base =
                st + (warp_m * 32 + (lane & 15)) * 80 + ((lane >> 4) * 16) + k16 * 32;
            const int bg = lane >> 3;
            const uint32_t b_base =
                st + 2 * TILE_B +
                (warp_n * 64 + (bg >> 1) * 8 + (lane & 7)) * 80 +
                ((bg & 1) * 16) + k16 * 32;
#pragma unroll
            for (int mt = 0; mt < 2; mt++) {
                ldsm_x4(a_base + mt * 16 * 80, ah[mt]);
                ldsm_x4(a_base + TILE_B + mt * 16 * 80, al[mt]);
            }
#pragma unroll
            for (int ntp = 0; ntp < 4; ntp++) {
                ldsm_x4(b_base + ntp * 16 * 80, bh[ntp]);
                ldsm_x4(b_base + TILE_B + ntp * 16 * 80, bl[ntp]);
            }
            // ---- 48 MMAs, same-acc reuse distance 16 ----
#pragma unroll
            for (int mt = 0; mt < 2; mt++)
#pragma unroll
                for (int ntp = 0; ntp < 4; ntp++)
#pragma unroll
                    for (int hf = 0; hf < 2; hf++)
                        mma_bf16(acc[mt][ntp * 2 + hf], ah[mt],
                                 bh[ntp][hf * 2], bh[ntp][hf * 2 + 1]);
#pragma unroll
            for (int mt = 0; mt < 2; mt++)
#pragma unroll
                for (int ntp = 0; ntp < 4; ntp++)
#pragma unroll
                    for (int hf = 0; hf < 2; hf++)
                        mma_bf16(acc[mt][ntp * 2 + hf], ah[mt],
                                 bl[ntp][hf * 2], bl[ntp][hf * 2 + 1]);
#pragma unroll
            for (int mt = 0; mt < 2; mt++)
#pragma unroll
                for (int ntp = 0; ntp < 4; ntp++)
#pragma unroll
                    for (int hf = 0; hf < 2; hf++)
                        mma_bf16(acc[mt][ntp * 2 + hf], al[mt],
                                 bh[ntp][hf * 2], bh[ntp][hf * 2 + 1]);
        }
        __syncthreads();
    }

#pragma unroll
    for (int mt = 0; mt < 2; mt++) {
#pragma unroll
        for (int nt = 0; nt < 8; nt++) {
            const int colg = n0 + warp_n * 64 + nt * 8 + (lane & 3) * 2;
            const float2 bv = *reinterpret_cast<const float2*>(&args.bias[z][colg]);
#pragma unroll
            for (int half = 0; half < 2; half++) {
                const int rowg = m0 + warp_m * 32 + mt * 16 + (lane >> 2) + half * 8;
                const float ox = acc[mt][nt][half * 2 + 0] + bv.x;
                const float oy = acc[mt][nt][half * 2 + 1] + bv.y;
                if (MODE == 1) {
                    const int b = rowg >> 11, s = rowg & 2047;
                    const int h = colg >> 6, d = colg & 63;
                    const size_t idx = (((size_t)b * NHEAD + h) * SEQ + s) * DHEAD + d;
                    uint32_t hi, lo;
                    split2(ox, oy, hi, lo);
                    *reinterpret_cast<uint32_t*>(args.Ch[z] + idx) = hi;
                    *reinterpret_cast<uint32_t*>(args.Cl[z] + idx) = lo;
                } else {
                    float2 o; o.x = ox; o.y = oy;
                    *reinterpret_cast<float2*>(&args.C[z][(size_t)rowg * GN + colg]) = o;
                }
            }
        }
    }
}

// ---------------------------------------------------------------------------
// Tensor-core flash attention (causal), bf16 hi/lo, front-loaded fragments.
// ---------------------------------------------------------------------------
constexpr int AQ_BYTES  = 128 * 144;
constexpr int AKV_BYTES = 64 * 144;
constexpr int ASTAGE    = 4 * AKV_BYTES;
constexpr int ATT_SMEM  = 2 * AQ_BYTES + 2 * ASTAGE;  // 110592

__global__ void __launch_bounds__(256, 2) attn_mma(
    const __nv_bfloat16* __restrict__ Qh, const __nv_bfloat16* __restrict__ Ql,
    const __nv_bfloat16* __restrict__ Kh, const __nv_bfloat16* __restrict__ Kl,
    const __nv_bfloat16* __restrict__ Vh, const __nv_bfloat16* __restrict__ Vl,
    __nv_bfloat16* __restrict__ Ch, __nv_bfloat16* __restrict__ Cl)
{
    extern __shared__ __align__(128) uint8_t smem[];
    const uint32_t sbase = smem_u32(smem);
    const int tid = threadIdx.x, lane = tid & 31, wm = tid >> 5;
    const int qb = gridDim.x - 1 - blockIdx.x;
    const int bh = blockIdx.y;
    const size_t base = (size_t)bh * SEQ * DHEAD;
    const int nkb = 2 * qb + 2;

    {
        const int r = tid >> 1, half = tid & 1;
        const size_t g = base + (size_t)(qb * 128 + r) * DHEAD + half * 32;
        const uint32_t d = sbase + r * 144 + half * 64;
#pragma unroll
        for (int i = 0; i < 4; i++) {
            cp16(d + i * 16, Qh + g + i * 8);
            cp16(d + AQ_BYTES + i * 16, Ql + g + i * 8);
        }
    }
    auto loadKV = [&](int kb) {
        const uint32_t ss = sbase + 2 * AQ_BYTES + (kb & 1) * ASTAGE;
        const int r = tid >> 2, seg = tid & 3;
        const size_t g = base + (size_t)(kb * 64 + r) * DHEAD + seg * 16;
        const uint32_t d = ss + r * 144 + seg * 32;
        cp16(d, Kh + g);                      cp16(d + 16, Kh + g + 8);
        cp16(d + AKV_BYTES, Kl + g);          cp16(d + AKV_BYTES + 16, Kl + g + 8);
        cp16(d + 2 * AKV_BYTES, Vh + g);      cp16(d + 2 * AKV_BYTES + 16, Vh + g + 8);
        cp16(d + 3 * AKV_BYTES, Vl + g);      cp16(d + 3 * AKV_BYTES + 16, Vl + g + 8);
    };
    loadKV(0);
    CP_COMMIT();

    float m0 = -1e30f, m1 = -1e30f, l0 = 0.f, l1 = 0.f;
    float acco[8][4];
#pragma unroll
    for (int nt = 0; nt < 8; nt++)
#pragma unroll
        for (int e = 0; e < 4; e++) acco[nt][e] = 0.f;

    const int bg = lane >> 3;
    const uint32_t aq = sbase + (wm * 16 + (lane & 15)) * 144 + (lane >> 4) * 16;

    for (int kb = 0; kb < nkb; kb++) {
        if (kb + 1 < nkb) loadKV(kb + 1);
        CP_COMMIT();
        CP_WAIT1();
        __syncthreads();
        const uint32_t ss = sbase + 2 * AQ_BYTES + (kb & 1) * ASTAGE;

        // ---- S = Q K^T: per kc front-load 10 ldsm, 24 MMAs distance 8 ----
        float accs[8][4];
#pragma unroll
        for (int nt = 0; nt < 8; nt++)
#pragma unroll
            for (int e = 0; e < 4; e++) accs[nt][e] = 0.f;

        const uint32_t kbase = ss + ((bg >> 1) * 8 + (lane & 7)) * 144 + (bg & 1) * 16;
#pragma unroll
        for (int kc = 0; kc < 4; kc++) {
            uint32_t qh4[4], ql4[4], kh4[4][4], kl4[4][4];
            ldsm_x4(aq + kc * 32, qh4);
            ldsm_x4(aq + AQ_BYTES + kc * 32, ql4);
#pragma unroll
            for (int ntp = 0; ntp < 4; ntp++) {
                ldsm_x4(kbase + ntp * 16 * 144 + kc * 32, kh4[ntp]);
                ldsm_x4(kbase + AKV_BYTES + ntp * 16 * 144 + kc * 32, kl4[ntp]);
            }
#pragma unroll
            for (int ntp = 0; ntp < 4; ntp++)
#pragma unroll
                for (int hf = 0; hf < 2; hf++)
                    mma_bf16(accs[ntp * 2 + hf], qh4,
                             kh4[ntp][hf * 2], kh4[ntp][hf * 2 + 1]);
#pragma unroll
            for (int ntp = 0; ntp < 4; ntp++)
#pragma unroll
                for (int hf = 0; hf < 2; hf++)
                    mma_bf16(accs[ntp * 2 + hf], qh4,
                             kl4[ntp][hf * 2], kl4[ntp][hf * 2 + 1]);
#pragma unroll
            for (int ntp = 0; ntp < 4; ntp++)
#pragma unroll
                for (int hf = 0; hf < 2; hf++)
                    mma_bf16(accs[ntp * 2 + hf], ql4,
                             kh4[ntp][hf * 2], kh4[ntp][hf * 2 + 1]);
        }

        // ---- online softmax ----
        const int r0 = qb * 128 + wm * 16 + (lane >> 2);
        const bool needMask = (kb * 64 + 63 > qb * 128 + wm * 16);
        float mx0 = -1e30f, mx1 = -1e30f;
#pragma unroll
        for (int nt = 0; nt < 8; nt++) {
#pragma unroll
            for (int e = 0; e < 4; e++) {
                float s = accs[nt][e] * 0.125f;
                if (needMask) {
                    const int col = kb * 64 + nt * 8 + (lane & 3) * 2 + (e & 1);
                    const int row = r0 + (e >> 1) * 8;
                    if (col > row) s = -1e30f;
                }
                accs[nt][e] = s;
            }
            mx0 = fmaxf(mx0, fmaxf(accs[nt][0], accs[nt][1]));
            mx1 = fmaxf(mx1, fmaxf(accs[nt][2], accs[nt][3]));
        }
        mx0 = fmaxf(mx0, __shfl_xor_sync(0xffffffffu, mx0, 1));
        mx0 = fmaxf(mx0, __shfl_xor_sync(0xffffffffu, mx0, 2));
        mx1 = fmaxf(mx1, __shfl_xor_sync(0xffffffffu, mx1, 1));
        mx1 = fmaxf(mx1, __shfl_xor_sync(0xffffffffu, mx1, 2));
        const float mn0 = fmaxf(m0, mx0), mn1 = fmaxf(m1, mx1);
        const float al0 = __expf(m0 - mn0), al1 = __expf(m1 - mn1);
        float rs0 = 0.f, rs1 = 0.f;
#pragma unroll
        for (int nt = 0; nt < 8; nt++) {
            accs[nt][0] = __expf(accs[nt][0] - mn0);
            accs[nt][1] = __expf(accs[nt][1] - mn0);
            accs[nt][2] = __expf(accs[nt][2] - mn1);
            accs[nt][3] = __expf(accs[nt][3] - mn1);
            rs0 += accs[nt][0] + accs[nt][1];
            rs1 += accs[nt][2] + accs[nt][3];
        }
        rs0 += __shfl_xor_sync(0xffffffffu, rs0, 1);
        rs0 += __shfl_xor_sync(0xffffffffu, rs0, 2);
        rs1 += __shfl_xor_sync(0xffffffffu, rs1, 1);
        rs1 += __shfl_xor_sync(0xffffffffu, rs1, 2);
        l0 = l0 * al0 + rs0; l1 = l1 * al1 + rs1;
        m0 = mn0; m1 = mn1;
#pragma unroll
        for (int nt = 0; nt < 8; nt++) {
            acco[nt][0] *= al0; acco[nt][1] *= al0;
            acco[nt][2] *= al1; acco[nt][3] *= al1;
        }

        // ---- O += P V: per c front-load 8 V-ldsm, 24 MMAs distance 8 ----
#pragma unroll
        for (int c = 0; c < 4; c++) {
            uint32_t pah[4], pal[4];
            split2(accs[2 * c][0], accs[2 * c][1], pah[0], pal[0]);
            split2(accs[2 * c][2], accs[2 * c][3], pah[1], pal[1]);
            split2(accs[2 * c + 1][0], accs[2 * c + 1][1], pah[2], pal[2]);
            split2(accs[2 * c + 1][2], accs[2 * c + 1][3], pah[3], pal[3]);
            const uint32_t vb = ss + 2 * AKV_BYTES +
                (c * 16 + (bg & 1) * 8 + (lane & 7)) * 144 + (bg >> 1) * 16;
            uint32_t vh4[4][4], vl4[4][4];
#pragma unroll
            for (int dp = 0; dp < 4; dp++) {
                ldsm_x4_t(vb + dp * 32, vh4[dp]);
                ldsm_x4_t(vb + AKV_BYTES + dp * 32, vl4[dp]);
            }
#pragma unroll
            for (int dp = 0; dp < 4; dp++)
#pragma unroll
                for (int hf = 0; hf < 2; hf++)
                    mma_bf16(acco[dp * 2 + hf], pah,
                             vh4[dp][hf * 2], vh4[dp][hf * 2 + 1]);
#pragma unroll
            for (int dp = 0; dp < 4; dp++)
#pragma unroll
                for (int hf = 0; hf < 2; hf++)
                    mma_bf16(acco[dp * 2 + hf], pah,
                             vl4[dp][hf * 2], vl4[dp][hf * 2 + 1]);
#pragma unroll
            for (int dp = 0; dp < 4; dp++)
#pragma unroll
                for (int hf = 0; hf < 2; hf++)
                    mma_bf16(acco[dp * 2 + hf], pal,
                             vh4[dp][hf * 2], vh4[dp][hf * 2 + 1]);
        }
        __syncthreads();
    }

    // ---- epilogue ----
    const int b = bh >> 4, h = bh & 15;
    const float i0 = 1.f / l0, i1 = 1.f / l1;
    const size_t tok = (size_t)b * SEQ + qb * 128 + wm * 16 + (lane >> 2);
#pragma unroll
    for (int nt = 0; nt < 8; nt++) {
        const int d0 = h * DHEAD + nt * 8 + (lane & 3) * 2;
        uint32_t hi, lo;
        split2(acco[nt][0] * i0, acco[nt][1] * i0, hi, lo);
        *reinterpret_cast<uint32_t*>(Ch + tok * DMODEL + d0) = hi;
        *reinterpret_cast<uint32_t*>(Cl + tok * DMODEL + d0) = lo;
        split2(acco[nt][2] * i1, acco[nt][3] * i1, hi, lo);
        *reinterpret_cast<uint32_t*>(Ch + (tok + 8) * DMODEL + d0) = hi;
        *reinterpret_cast<uint32_t*>(Cl + (tok + 8) * DMODEL + d0) = lo;
    }
}

// ---------------------------------------------------------------------------
extern "C" void kernel_launch(void* const* d_in, const int* in_sizes, int n_in,
                              void* d_out, int out_size)
{
    const float* q   = (const float*)d_in[0];
    const float* k   = (const float*)d_in[1];
    const float* v   = (const float*)d_in[2];
    const float* w_q = (const float*)d_in[4];
    const float* b_q = (const float*)d_in[5];
    const float* w_k = (const float*)d_in[6];
    const float* b_k = (const float*)d_in[7];
    const float* w_v = (const float*)d_in[8];
    const float* b_v = (const float*)d_in[9];
    const float* w_o = (const float*)d_in[10];
    const float* b_o = (const float*)d_in[11];
    float* out = (float*)d_out;

    __nv_bfloat16 *ah, *al, *wh, *wl, *ch, *cl;
    __nv_bfloat16 *qh, *ql, *kh, *kl, *vh, *vl;
    cudaGetSymbolAddress((void**)&ah, g_ah);
    cudaGetSymbolAddress((void**)&al, g_al);
    cudaGetSymbolAddress((void**)&wh, g_wh);
    cudaGetSymbolAddress((void**)&wl, g_wl);
    cudaGetSymbolAddress((void**)&ch, g_ch);
    cudaGetSymbolAddress((void**)&cl, g_cl);
    cudaGetSymbolAddress((void**)&qh, g_qh);
    cudaGetSymbolAddress((void**)&ql, g_ql);
    cudaGetSymbolAddress((void**)&kh, g_kh2);
    cudaGetSymbolAddress((void**)&kl, g_kl2);
    cudaGetSymbolAddress((void**)&vh, g_vh2);
    cudaGetSymbolAddress((void**)&vl, g_vl2);

    static bool attr_set = false;
    if (!attr_set) {
        cudaFuncSetAttribute(gemm_mma<0>,
                             cudaFuncAttributeMaxDynamicSharedMemorySize, GEMM_SMEM);
        cudaFuncSetAttribute(gemm_mma<1>,
                             cudaFuncAttributeMaxDynamicSharedMemorySize, GEMM_SMEM);
        cudaFuncSetAttribute(attn_mma,
                             cudaFuncAttributeMaxDynamicSharedMemorySize, ATT_SMEM);
        attr_set = true;
    }

    const int nX = GM * GK;
    const int nW = GN * GK;

    SplitArgs sa;
    sa.src[0] = q;   sa.hi[0] = ah;                  sa.lo[0] = al;
    sa.src[1] = k;   sa.hi[1] = ah + (size_t)nX;     sa.lo[1] = al + (size_t)nX;
    sa.src[2] = v;   sa.hi[2] = ah + 2 * (size_t)nX; sa.lo[2] = al + 2 * (size_t)nX;
    sa.src[3] = w_q; sa.hi[3] = wh;                  sa.lo[3] = wl;
    sa.src[4] = w_k; sa.hi[4] = wh + (size_t)nW;     sa.lo[4] = wl + (size_t)nW;
    sa.src[5] = w_v; sa.hi[5] = wh + 2 * (size_t)nW; sa.lo[5] = wl + 2 * (size_t)nW;
    sa.src[6] = w_o; sa.hi[6] = wh + 3 * (size_t)nW; sa.lo[6] = wl + 3 * (size_t)nW;
    split_all_kernel<<<3 * 4096 + 4 * 1024, 256>>>(sa);

    GemmBatch gb;
    gb.Ah[0] = ah;                  gb.Al[0] = al;
    gb.Ah[1] = ah + (size_t)nX;     gb.Al[1] = al + (size_t)nX;
    gb.Ah[2] = ah + 2 * (size_t)nX; gb.Al[2] = al + 2 * (size_t)nX;
    gb.Wh[0] = wh;                  gb.Wl[0] = wl;
    gb.Wh[1] = wh + (size_t)nW;     gb.Wl[1] = wl + (size_t)nW;
    gb.Wh[2] = wh + 2 * (size_t)nW; gb.Wl[2] = wl + 2 * (size_t)nW;
    gb.bias[0] = b_q; gb.bias[1] = b_k; gb.bias[2] = b_v;
    gb.C[0] = gb.C[1] = gb.C[2] = nullptr;
    gb.Ch[0] = qh; gb.Cl[0] = ql;
    gb.Ch[1] = kh; gb.Cl[1] = kl;
    gb.Ch[2] = vh; gb.Cl[2] = vl;
    gemm_mma<1><<<dim3(GN / 128, GM / 128, 3), 256, GEMM_SMEM>>>(gb);

    attn_mma<<<dim3(SEQ / 128, BSZ * NHEAD), 256, ATT_SMEM>>>(
        qh, ql, kh, kl, vh, vl, ch, cl);

    GemmBatch go;
    go.Ah[0] = ch; go.Al[0] = cl;
    go.Wh[0] = wh + 3 * (size_t)nW; go.Wl[0] = wl + 3 * (size_t)nW;
    go.bias[0] = b_o;
    go.C[0] = out;
    go.Ch[0] = nullptr; go.Cl[0] = nullptr;
    go.Ah[1] = go.Ah[2] = nullptr; go.Al[1] = go.Al[2] = nullptr;
    go.Wh[1] = go.Wh[2] = nullptr; go.Wl[1] = go.Wl[2] = nullptr;
    go.bias[1] = go.bias[2] = nullptr;
    go.C[1] = go.C[2] = nullptr;
    go.Ch[1] = go.Ch[2] = nullptr; go.Cl[1] = go.Cl[2] = nullptr;
    gemm_mma<0><<<dim3(GN / 128, GM / 128, 1), 256, GEMM_SMEM>>>(go);
}